// round 5
// baseline (speedup 1.0000x reference)
#include <cuda_runtime.h>
#include <cstdint>

#define NB 131072
#define NA 65536
#define NM 2048
#define DH 300
#define AF 133
#define K1 147
#define GF 128
#define OUTC 428

#define KP1 160
#define KP2 320
#define KP3 448

// ---------------- device scratch ----------------
__device__ __align__(16) float g_Af1[(size_t)NB * KP1];   // padded f_ini (tf32)
__device__ __align__(16) float g_AtomF[(size_t)NA * 136]; // padded atom_features (tf32)
__device__ __align__(16) float g_W1[320 * KP1];
__device__ __align__(16) float g_W2[320 * KP2];
__device__ __align__(16) float g_W3[320 * KP3];
__device__ __align__(16) float g_inp[(size_t)NB * DH];
__device__ __align__(16) float g_m1 [(size_t)NB * DH];
__device__ __align__(16) float g_h2 [(size_t)NB * DH];

// ---------------- helpers ----------------
__device__ __forceinline__ uint32_t s2u(const void* p) {
    uint32_t a;
    asm("{ .reg .u64 t; cvta.to.shared.u64 t, %1; cvt.u32.u64 %0, t; }"
        : "=r"(a) : "l"(p));
    return a;
}
__device__ __forceinline__ void cpa16(uint32_t s, const void* g) {
    asm volatile("cp.async.cg.shared.global [%0], [%1], 16;" :: "r"(s), "l"(g));
}
#define CP_COMMIT() asm volatile("cp.async.commit_group;" ::: "memory")
#define CP_WAIT0()  asm volatile("cp.async.wait_group 0;" ::: "memory")

__device__ __forceinline__ float rtf32(float x) {
    uint32_t u;
    asm("cvt.rna.tf32.f32 %0, %1;" : "=r"(u) : "f"(x));
    return __uint_as_float(u);
}
__device__ __forceinline__ void mma_tf32(float* c, const float* a, const float* b) {
    asm volatile(
        "mma.sync.aligned.m16n8k8.row.col.f32.tf32.tf32.f32 "
        "{%0,%1,%2,%3}, {%4,%5,%6,%7}, {%8,%9}, {%0,%1,%2,%3};"
        : "+f"(c[0]), "+f"(c[1]), "+f"(c[2]), "+f"(c[3])
        : "r"(__float_as_uint(a[0])), "r"(__float_as_uint(a[1])),
          "r"(__float_as_uint(a[2])), "r"(__float_as_uint(a[3])),
          "r"(__float_as_uint(b[0])), "r"(__float_as_uint(b[1])));
}

// ---------------- weight prep: W[K x 300] -> Wt[320 x KP] (n-major, tf32) ----------------
template <int MODE>
__global__ void prep_w(const float* __restrict__ W) {
    constexpr int KP = (MODE == 1) ? KP1 : (MODE == 2) ? KP2 : KP3;
    float* B = (MODE == 1) ? g_W1 : (MODE == 2) ? g_W2 : g_W3;
    int idx = blockIdx.x * 256 + threadIdx.x;
    if (idx >= 320 * KP) return;
    int n = idx / KP, k = idx % KP;
    int src;
    if (MODE == 3) src = (k < 133) ? k : (k >= 136 && k < 436) ? k - 3 : -1;
    else if (MODE == 1) src = (k < K1) ? k : -1;
    else src = (k < DH) ? k : -1;
    float v = (n < 300 && src >= 0) ? W[src * 300 + n] : 0.f;
    B[(size_t)n * KP + k] = rtf32(v);
}

__global__ void pad1(const float* __restrict__ F) {
    int idx = blockIdx.x * 256 + threadIdx.x;
    if (idx >= NB * 40) return;
    int r = idx / 40, k = (idx % 40) * 4;
    float4 v;
    v.x = (k + 0 < K1) ? rtf32(F[(size_t)r * K1 + k + 0]) : 0.f;
    v.y = (k + 1 < K1) ? rtf32(F[(size_t)r * K1 + k + 1]) : 0.f;
    v.z = (k + 2 < K1) ? rtf32(F[(size_t)r * K1 + k + 2]) : 0.f;
    v.w = (k + 3 < K1) ? rtf32(F[(size_t)r * K1 + k + 3]) : 0.f;
    *(float4*)&g_Af1[(size_t)r * KP1 + k] = v;
}

__global__ void pad3(const float* __restrict__ AFt) {
    int idx = blockIdx.x * 256 + threadIdx.x;
    if (idx >= NA * 136) return;
    int r = idx / 136, k = idx % 136;
    float v = (k < AF) ? rtf32(AFt[(size_t)r * AF + k]) : 0.f;
    g_AtomF[(size_t)r * 136 + k] = v;
}

// ---------------- gather1: m1 = sum_j relu(inp[map[j]]) ----------------
__global__ void gather_relu(const int* __restrict__ map) {
    int idx = blockIdx.x * 256 + threadIdx.x;
    if (idx >= NB * 75) return;
    int r = idx / 75, c = idx % 75;
    int4 m = ((const int4*)map)[r];
    const float4* S = (const float4*)g_inp;
    float4 a = S[(size_t)m.x * 75 + c];
    float4 b = S[(size_t)m.y * 75 + c];
    float4 cc = S[(size_t)m.z * 75 + c];
    float4 d = S[(size_t)m.w * 75 + c];
    float4 o;
    o.x = fmaxf(a.x, 0.f) + fmaxf(b.x, 0.f) + fmaxf(cc.x, 0.f) + fmaxf(d.x, 0.f);
    o.y = fmaxf(a.y, 0.f) + fmaxf(b.y, 0.f) + fmaxf(cc.y, 0.f) + fmaxf(d.y, 0.f);
    o.z = fmaxf(a.z, 0.f) + fmaxf(b.z, 0.f) + fmaxf(cc.z, 0.f) + fmaxf(d.z, 0.f);
    o.w = fmaxf(a.w, 0.f) + fmaxf(b.w, 0.f) + fmaxf(cc.w, 0.f) + fmaxf(d.w, 0.f);
    ((float4*)g_m1)[(size_t)r * 75 + c] = o;
}

// ---------------- gather-fused TF32 GEMM ----------------
// BM=128, BN=160, BK=32, 256 thr, 2 smem stages.
// A produced by manual LDG(+4-way gather-sum)->regs->STS; B via cp.async.
#define STG  41472
#define BOFF 18432

template <int MODE, int KP>
__global__ void __launch_bounds__(256)
mm_tf32(const float* __restrict__ bias, float* __restrict__ dOut,
        const int* __restrict__ gmap) {
    constexpr int NCH = KP / 32;
    const float* __restrict__ Wt = (MODE == 1) ? g_W1 : (MODE == 2) ? g_W2 : g_W3;

    extern __shared__ __align__(16) char smem[];
    const uint32_t sb = s2u(smem);
    const int tid = threadIdx.x, w = tid >> 5, lane = tid & 31;
    const int wr = w & 1, wc = w >> 1;       // warp tile 64x40
    const int rowBase = blockIdx.y * 128;
    const int colBase = blockIdx.x * 160;

    float acc[4][5][4];
#pragma unroll
    for (int i = 0; i < 4; i++)
#pragma unroll
        for (int j = 0; j < 5; j++)
#pragma unroll
            for (int q = 0; q < 4; q++) acc[i][j][q] = 0.f;

    // ---- A producer state ----
    const int arow = tid & 127;          // this thread's A row within tile
    const int f4sel = tid >> 7;          // 0: cols 0..15, 1: cols 16..31 of chunk
    int4 m = make_int4(0, 0, 0, 0);
    if (MODE >= 2) m = ((const int4*)gmap)[rowBase + arow];

    float4 rbuf[4];

    auto loadA = [&](int c) {
        const int k0c = c * 32 + f4sel * 16;
#pragma unroll
        for (int q = 0; q < 4; q++) {
            const int k0 = k0c + q * 4;
            float4 v = make_float4(0.f, 0.f, 0.f, 0.f);
            if (MODE == 1) {
                v = *(const float4*)&g_Af1[(size_t)(rowBase + arow) * KP1 + k0];
            } else if (MODE == 2) {
                if (k0 < 300) {
                    const float4* S = (const float4*)g_m1;
                    const int c4 = k0 >> 2;
                    float4 a = S[(size_t)m.x * 75 + c4];
                    float4 b = S[(size_t)m.y * 75 + c4];
                    float4 cc = S[(size_t)m.z * 75 + c4];
                    float4 d = S[(size_t)m.w * 75 + c4];
                    v.x = rtf32(a.x + b.x + cc.x + d.x);
                    v.y = rtf32(a.y + b.y + cc.y + d.y);
                    v.z = rtf32(a.z + b.z + cc.z + d.z);
                    v.w = rtf32(a.w + b.w + cc.w + d.w);
                }
            } else {
                if (k0 < 136) {
                    v = *(const float4*)&g_AtomF[(size_t)(rowBase + arow) * 136 + k0];
                } else if (k0 < 436) {
                    const float4* S = (const float4*)g_h2;
                    const int c4 = (k0 - 136) >> 2;
                    float4 a = S[(size_t)m.x * 75 + c4];
                    float4 b = S[(size_t)m.y * 75 + c4];
                    float4 cc = S[(size_t)m.z * 75 + c4];
                    float4 d = S[(size_t)m.w * 75 + c4];
                    v.x = rtf32(a.x + b.x + cc.x + d.x);
                    v.y = rtf32(a.y + b.y + cc.y + d.y);
                    v.z = rtf32(a.z + b.z + cc.z + d.z);
                    v.w = rtf32(a.w + b.w + cc.w + d.w);
                }
            }
            rbuf[q] = v;
        }
    };
    auto stsA = [&](int st) {
        char* p = smem + st * STG + arow * 144 + f4sel * 64;
#pragma unroll
        for (int q = 0; q < 4; q++) *(float4*)(p + q * 16) = rbuf[q];
    };

    const int lrow = tid >> 3, lseg = tid & 7;
    auto loadB = [&](int c, int st) {
#pragma unroll
        for (int it = 0; it < 5; it++) {
            int row = lrow + it * 32;
            cpa16(sb + st * STG + BOFF + row * 144 + lseg * 16,
                  Wt + (size_t)(colBase + row) * KP + c * 32 + lseg * 4);
        }
    };

    // ---- prologue ----
    loadA(0); stsA(0);
    loadB(0, 0); CP_COMMIT();
    loadA(1);
    CP_WAIT0();
    __syncthreads();

    const uint32_t aBase = (wr * 64 + (lane >> 2)) * 144 + (lane & 3) * 4;
    const uint32_t bBase = BOFF + (wc * 40 + (lane >> 2)) * 144 + (lane & 3) * 4;

    for (int c = 0; c < NCH; c++) {
        const int stN = (c + 1) & 1;
        if (c + 1 < NCH) {
            stsA(stN);                 // stage free since end of iter c-1
            loadB(c + 1, stN); CP_COMMIT();
        }
        if (c + 2 < NCH) loadA(c + 2); // LDGs in flight during compute

        const char* stp = smem + (c & 1) * STG;
#pragma unroll
        for (int k8 = 0; k8 < 4; k8++) {
            float af[4][4], bfr[5][2];
#pragma unroll
            for (int mt = 0; mt < 4; mt++) {
                const char* p = stp + aBase + mt * (16 * 144) + k8 * 32;
                af[mt][0] = *(const float*)p;
                af[mt][1] = *(const float*)(p + 8 * 144);
                af[mt][2] = *(const float*)(p + 16);
                af[mt][3] = *(const float*)(p + 8 * 144 + 16);
            }
#pragma unroll
            for (int nt = 0; nt < 5; nt++) {
                const char* p = stp + bBase + nt * (8 * 144) + k8 * 32;
                bfr[nt][0] = *(const float*)p;
                bfr[nt][1] = *(const float*)(p + 16);
            }
#pragma unroll
            for (int mt = 0; mt < 4; mt++)
#pragma unroll
                for (int nt = 0; nt < 5; nt++)
                    mma_tf32(acc[mt][nt], af[mt], bfr[nt]);
        }
        CP_WAIT0();
        __syncthreads();
    }

    if (MODE == 3) {
        // fused per-molecule mean readout: 128 rows = 4 molecules
        const int molBase = blockIdx.y * 4 + wr * 2;
#pragma unroll
        for (int mtb = 0; mtb < 4; mtb += 2) {
#pragma unroll
            for (int nt = 0; nt < 5; nt++) {
                const int col2 = colBase + wc * 40 + nt * 8 + (lane & 3) * 2;
                float b0 = 0.f, b1 = 0.f;
                if (col2 < DH) { b0 = bias[col2]; b1 = bias[col2 + 1]; }
                float s0 = 0.f, s1 = 0.f;
#pragma unroll
                for (int p = 0; p < 2; p++) {
#pragma unroll
                    for (int h = 0; h < 2; h++) {
                        s0 += fmaxf(acc[mtb + p][nt][h * 2]     + b0, 0.f);
                        s1 += fmaxf(acc[mtb + p][nt][h * 2 + 1] + b1, 0.f);
                    }
                }
#pragma unroll
                for (int off = 16; off >= 4; off >>= 1) {
                    s0 += __shfl_down_sync(0xFFFFFFFFu, s0, off);
                    s1 += __shfl_down_sync(0xFFFFFFFFu, s1, off);
                }
                if (lane < 4) {
                    const int colw = colBase + wc * 40 + nt * 8 + lane * 2;
                    if (colw < DH) {
                        const int mol = molBase + (mtb >> 1);
                        float2 v;
                        v.x = s0 * 0.03125f;
                        v.y = s1 * 0.03125f;
                        *(float2*)&dOut[(size_t)mol * OUTC + colw] = v;
                    }
                }
            }
        }
    } else {
        float* __restrict__ OUTp = (MODE == 1) ? g_inp : g_h2;
        const int crow = lane >> 2, cc0 = (lane & 3) * 2;
#pragma unroll
        for (int mt = 0; mt < 4; mt++) {
#pragma unroll
            for (int nt = 0; nt < 5; nt++) {
                const int col = colBase + wc * 40 + nt * 8 + cc0;
                if (col >= DH) continue;
#pragma unroll
                for (int half = 0; half < 2; half++) {
                    const int grow = rowBase + wr * 64 + mt * 16 + crow + half * 8;
                    const size_t o = (size_t)grow * DH + col;
                    float v0 = acc[mt][nt][half * 2];
                    float v1 = acc[mt][nt][half * 2 + 1];
                    if (MODE == 2) {
                        float2 pv = *(const float2*)&g_inp[o];
                        v0 = fmaxf(pv.x + v0, 0.f);
                        v1 = fmaxf(pv.y + v1, 0.f);
                    }
                    float2 r; r.x = v0; r.y = v1;
                    *(float2*)&OUTp[o] = r;
                }
            }
        }
    }
}

// ---------------- global-feature concat ----------------
__global__ void glob_copy(const float* __restrict__ g, float* __restrict__ out) {
    int idx = blockIdx.x * 256 + threadIdx.x;
    if (idx >= NM * 32) return;
    int mol = idx >> 5, j4 = idx & 31;
    float4 v = ((const float4*)g)[mol * 32 + j4];
    *(float4*)&out[(size_t)mol * OUTC + 300 + 4 * j4] = v;
}

// ---------------- launch ----------------
extern "C" void kernel_launch(void* const* d_in, const int* in_sizes, int n_in,
                              void* d_out, int out_size) {
    const float* atom_features   = (const float*)d_in[0];
    const float* f_ini           = (const float*)d_in[1];
    const float* global_features = (const float*)d_in[2];
    const float* W_i             = (const float*)d_in[3];
    const float* W_h             = (const float*)d_in[4];
    const float* W_o             = (const float*)d_in[5];
    const float* b_o             = (const float*)d_in[6];
    const int*   a2ib            = (const int*)d_in[7];
    const int*   mapping         = (const int*)d_in[8];
    float* out = (float*)d_out;

    const int smemSz = 2 * STG;   // 82944
    static bool cfg = false;
    if (!cfg) {
        cudaFuncSetAttribute(mm_tf32<1, KP1>, cudaFuncAttributeMaxDynamicSharedMemorySize, smemSz);
        cudaFuncSetAttribute(mm_tf32<2, KP2>, cudaFuncAttributeMaxDynamicSharedMemorySize, smemSz);
        cudaFuncSetAttribute(mm_tf32<3, KP3>, cudaFuncAttributeMaxDynamicSharedMemorySize, smemSz);
        cfg = true;
    }

    glob_copy<<<(NM * 32 + 255) / 256, 256>>>(global_features, out);
    prep_w<1><<<(320 * KP1 + 255) / 256, 256>>>(W_i);
    prep_w<2><<<(320 * KP2 + 255) / 256, 256>>>(W_h);
    prep_w<3><<<(320 * KP3 + 255) / 256, 256>>>(W_o);
    pad1<<<(NB * 40 + 255) / 256, 256>>>(f_ini);
    pad3<<<(NA * 136 + 255) / 256, 256>>>(atom_features);

    // 1) inp = f_ini @ W_i
    mm_tf32<1, KP1><<<dim3(2, NB / 128), 256, smemSz>>>(nullptr, nullptr, nullptr);
    // 2) m1 = sum relu(inp[mapping])
    gather_relu<<<(NB * 75 + 255) / 256, 256>>>(mapping);
    // 3+4) h2 = relu(inp + (sum m1[mapping]) @ W_h)   [gather fused into A-path]
    mm_tf32<2, KP2><<<dim3(2, NB / 128), 256, smemSz>>>(nullptr, nullptr, mapping);
    // 5+6) atoms_h = relu([atomF | sum h2[a2ib]] @ W_o + b_o) + fused mean readout
    mm_tf32<3, KP3><<<dim3(2, NA / 128), 256, smemSz>>>(b_o, out, a2ib);
}

// round 6
// speedup vs baseline: 1.1059x; 1.1059x over previous
#include <cuda_runtime.h>
#include <cstdint>

#define NB 131072
#define NA 65536
#define NM 2048
#define DH 300
#define AF 133
#define K1 147
#define GF 128
#define OUTC 428

#define KP1 160
#define KP2 320
#define KP3 448

// ---------------- device scratch ----------------
__device__ __align__(16) float g_W1[320 * KP1];
__device__ __align__(16) float g_W2[320 * KP2];
__device__ __align__(16) float g_W3[320 * KP3];
__device__ __align__(16) float g_inp[(size_t)NB * DH];
__device__ __align__(16) float g_m1 [(size_t)NB * DH];
__device__ __align__(16) float g_h2 [(size_t)NB * DH];

// ---------------- helpers ----------------
__device__ __forceinline__ uint32_t s2u(const void* p) {
    uint32_t a;
    asm("{ .reg .u64 t; cvta.to.shared.u64 t, %1; cvt.u32.u64 %0, t; }"
        : "=r"(a) : "l"(p));
    return a;
}
__device__ __forceinline__ void cpa16(uint32_t s, const void* g) {
    asm volatile("cp.async.cg.shared.global [%0], [%1], 16;" :: "r"(s), "l"(g));
}
#define CP_COMMIT() asm volatile("cp.async.commit_group;" ::: "memory")
#define CP_WAIT0()  asm volatile("cp.async.wait_group 0;" ::: "memory")

__device__ __forceinline__ float rtf32(float x) {
    uint32_t u;
    asm("cvt.rna.tf32.f32 %0, %1;" : "=r"(u) : "f"(x));
    return __uint_as_float(u);
}
__device__ __forceinline__ void mma_tf32(float* c, const float* a, const float* b) {
    asm volatile(
        "mma.sync.aligned.m16n8k8.row.col.f32.tf32.tf32.f32 "
        "{%0,%1,%2,%3}, {%4,%5,%6,%7}, {%8,%9}, {%0,%1,%2,%3};"
        : "+f"(c[0]), "+f"(c[1]), "+f"(c[2]), "+f"(c[3])
        : "r"(__float_as_uint(a[0])), "r"(__float_as_uint(a[1])),
          "r"(__float_as_uint(a[2])), "r"(__float_as_uint(a[3])),
          "r"(__float_as_uint(b[0])), "r"(__float_as_uint(b[1])));
}

// ---------------- weight prep (all 3 in one launch) ----------------
__global__ void prep_all(const float* __restrict__ W1s,
                         const float* __restrict__ W2s,
                         const float* __restrict__ W3s) {
    int idx = blockIdx.x * 256 + threadIdx.x;
    const int T1 = 320 * KP1, T2 = 320 * KP2;
    const float* W;
    float* B;
    int KP, mode;
    if (idx < T1) { W = W1s; B = g_W1; KP = KP1; mode = 1; }
    else if (idx < T1 + T2) { idx -= T1; W = W2s; B = g_W2; KP = KP2; mode = 2; }
    else {
        idx -= T1 + T2;
        if (idx >= 320 * KP3) return;
        W = W3s; B = g_W3; KP = KP3; mode = 3;
    }
    int n = idx / KP, k = idx % KP;
    int src;
    if (mode == 3) src = (k < 133) ? k : (k >= 136 && k < 436) ? k - 3 : -1;
    else if (mode == 1) src = (k < K1) ? k : -1;
    else src = (k < DH) ? k : -1;
    float v = (n < 300 && src >= 0) ? W[src * 300 + n] : 0.f;
    B[(size_t)n * KP + k] = rtf32(v);
}

// ---------------- gather1: m1 = sum_j relu(inp[map[j]]) ----------------
__global__ void gather_relu(const int* __restrict__ map) {
    int idx = blockIdx.x * 256 + threadIdx.x;
    if (idx >= NB * 75) return;
    int r = idx / 75, c = idx % 75;
    int4 m = ((const int4*)map)[r];
    const float4* S = (const float4*)g_inp;
    float4 a = S[(size_t)m.x * 75 + c];
    float4 b = S[(size_t)m.y * 75 + c];
    float4 cc = S[(size_t)m.z * 75 + c];
    float4 d = S[(size_t)m.w * 75 + c];
    float4 o;
    o.x = fmaxf(a.x, 0.f) + fmaxf(b.x, 0.f) + fmaxf(cc.x, 0.f) + fmaxf(d.x, 0.f);
    o.y = fmaxf(a.y, 0.f) + fmaxf(b.y, 0.f) + fmaxf(cc.y, 0.f) + fmaxf(d.y, 0.f);
    o.z = fmaxf(a.z, 0.f) + fmaxf(b.z, 0.f) + fmaxf(cc.z, 0.f) + fmaxf(d.z, 0.f);
    o.w = fmaxf(a.w, 0.f) + fmaxf(b.w, 0.f) + fmaxf(cc.w, 0.f) + fmaxf(d.w, 0.f);
    ((float4*)g_m1)[(size_t)r * 75 + c] = o;
}

// ---------------- fused TF32 GEMM ----------------
// BM=64, BN=320 (single column CTA), BK=32, 256 thr, 2 smem stages.
// A produced coalesced: warp owns 8 rows, lane owns one column of the chunk.
// MODE 1: A row <- f_ini (padded, tf32)            -> g_inp
// MODE 2: A row <- sum_j m1[map[j]] (tf32)         -> g_h2 = relu(g_inp + C)
// MODE 3: A row <- [atomF | sum_j h2[map[j]] | 0]  -> fused mean readout to out
#define STG   55296           // 64*144 + 320*144
#define BOFF  9216            // 64*144
#define SMAP  (2 * STG)       // int4 map table for 64 rows
#define SMTOT (SMAP + 1024)

template <int MODE, int KP>
__global__ void __launch_bounds__(256)
mm_tf32(const float* __restrict__ srcA,    // f_ini (MODE1) / atomF (MODE3)
        const int* __restrict__ gmap,
        const float* __restrict__ bias, float* __restrict__ dOut) {
    constexpr int NCH = KP / 32;
    const float* __restrict__ Wt = (MODE == 1) ? g_W1 : (MODE == 2) ? g_W2 : g_W3;

    extern __shared__ __align__(16) char smem[];
    const uint32_t sb = s2u(smem);
    const int tid = threadIdx.x, w = tid >> 5, lane = tid & 31;
    const int rowBase = blockIdx.x * 64;

    // stage map indices in smem (once)
    if (MODE >= 2 && tid < 64)
        ((int4*)(smem + SMAP))[tid] = ((const int4*)gmap)[rowBase + tid];
    __syncthreads();

    float acc[4][5][4];
#pragma unroll
    for (int i = 0; i < 4; i++)
#pragma unroll
        for (int j = 0; j < 5; j++)
#pragma unroll
            for (int q = 0; q < 4; q++) acc[i][j][q] = 0.f;

    float rbuf[8];

    auto loadA = [&](int c) {
        const int k = c * 32 + lane;
#pragma unroll
        for (int i = 0; i < 8; i++) {
            const int rloc = w * 8 + i;
            float v = 0.f;
            if (MODE == 1) {
                if (k < K1) v = rtf32(srcA[(size_t)(rowBase + rloc) * K1 + k]);
            } else if (MODE == 2) {
                if (k < 300) {
                    int4 m = ((const int4*)(smem + SMAP))[rloc];
                    v = rtf32(g_m1[(size_t)m.x * DH + k] + g_m1[(size_t)m.y * DH + k] +
                              g_m1[(size_t)m.z * DH + k] + g_m1[(size_t)m.w * DH + k]);
                }
            } else {
                if (k < AF) {
                    v = rtf32(srcA[(size_t)(rowBase + rloc) * AF + k]);
                } else if (k >= 136 && k < 436) {
                    int4 m = ((const int4*)(smem + SMAP))[rloc];
                    const int kk = k - 136;
                    v = rtf32(g_h2[(size_t)m.x * DH + kk] + g_h2[(size_t)m.y * DH + kk] +
                              g_h2[(size_t)m.z * DH + kk] + g_h2[(size_t)m.w * DH + kk]);
                }
            }
            rbuf[i] = v;
        }
    };
    auto stsA = [&](int st) {
        char* p = smem + st * STG + (w * 8) * 144 + lane * 4;
#pragma unroll
        for (int i = 0; i < 8; i++) *(float*)(p + i * 144) = rbuf[i];
    };

    const int lrow = tid >> 3, lseg = tid & 7;
    auto loadB = [&](int c, int st) {
#pragma unroll
        for (int it = 0; it < 10; it++) {
            int row = lrow + it * 32;
            cpa16(sb + st * STG + BOFF + row * 144 + lseg * 16,
                  Wt + (size_t)row * KP + c * 32 + lseg * 4);
        }
    };

    // ---- prologue ----
    loadA(0); stsA(0);
    loadB(0, 0); CP_COMMIT();
    loadA(1);
    CP_WAIT0();
    __syncthreads();

    const uint32_t aBase = (lane >> 2) * 144 + (lane & 3) * 4;
    const uint32_t bBase = BOFF + (w * 40 + (lane >> 2)) * 144 + (lane & 3) * 4;

    for (int c = 0; c < NCH; c++) {
        const int stN = (c + 1) & 1;
        if (c + 1 < NCH) {
            stsA(stN);
            loadB(c + 1, stN); CP_COMMIT();
        }
        if (c + 2 < NCH) loadA(c + 2);

        const char* stp = smem + (c & 1) * STG;
#pragma unroll
        for (int k8 = 0; k8 < 4; k8++) {
            float af[4][4], bfr[5][2];
#pragma unroll
            for (int mt = 0; mt < 4; mt++) {
                const char* p = stp + aBase + mt * (16 * 144) + k8 * 32;
                af[mt][0] = *(const float*)p;
                af[mt][1] = *(const float*)(p + 8 * 144);
                af[mt][2] = *(const float*)(p + 16);
                af[mt][3] = *(const float*)(p + 8 * 144 + 16);
            }
#pragma unroll
            for (int nt = 0; nt < 5; nt++) {
                const char* p = stp + bBase + nt * (8 * 144) + k8 * 32;
                bfr[nt][0] = *(const float*)p;
                bfr[nt][1] = *(const float*)(p + 16);
            }
#pragma unroll
            for (int mt = 0; mt < 4; mt++)
#pragma unroll
                for (int nt = 0; nt < 5; nt++)
                    mma_tf32(acc[mt][nt], af[mt], bfr[nt]);
        }
        CP_WAIT0();
        __syncthreads();
    }

    if (MODE == 3) {
        // fused per-molecule mean readout: 64 rows = 2 molecules
        const int molBase = blockIdx.x * 2;
#pragma unroll
        for (int mtb = 0; mtb < 4; mtb += 2) {
#pragma unroll
            for (int nt = 0; nt < 5; nt++) {
                const int col2 = w * 40 + nt * 8 + (lane & 3) * 2;
                float b0 = 0.f, b1 = 0.f;
                if (col2 < DH) { b0 = bias[col2]; b1 = bias[col2 + 1]; }
                float s0 = 0.f, s1 = 0.f;
#pragma unroll
                for (int p = 0; p < 2; p++) {
#pragma unroll
                    for (int h = 0; h < 2; h++) {
                        s0 += fmaxf(acc[mtb + p][nt][h * 2]     + b0, 0.f);
                        s1 += fmaxf(acc[mtb + p][nt][h * 2 + 1] + b1, 0.f);
                    }
                }
#pragma unroll
                for (int off = 16; off >= 4; off >>= 1) {
                    s0 += __shfl_down_sync(0xFFFFFFFFu, s0, off);
                    s1 += __shfl_down_sync(0xFFFFFFFFu, s1, off);
                }
                if (lane < 4) {
                    const int colw = w * 40 + nt * 8 + lane * 2;
                    if (colw < DH) {
                        const int mol = molBase + (mtb >> 1);
                        float2 v;
                        v.x = s0 * 0.03125f;
                        v.y = s1 * 0.03125f;
                        *(float2*)&dOut[(size_t)mol * OUTC + colw] = v;
                    }
                }
            }
        }
    } else {
        float* __restrict__ OUTp = (MODE == 1) ? g_inp : g_h2;
        const int crow = lane >> 2, cc0 = (lane & 3) * 2;
#pragma unroll
        for (int mt = 0; mt < 4; mt++) {
#pragma unroll
            for (int nt = 0; nt < 5; nt++) {
                const int col = w * 40 + nt * 8 + cc0;
                if (col >= DH) continue;
#pragma unroll
                for (int half = 0; half < 2; half++) {
                    const int grow = rowBase + mt * 16 + crow + half * 8;
                    const size_t o = (size_t)grow * DH + col;
                    float v0 = acc[mt][nt][half * 2];
                    float v1 = acc[mt][nt][half * 2 + 1];
                    if (MODE == 2) {
                        float2 pv = *(const float2*)&g_inp[o];
                        v0 = fmaxf(pv.x + v0, 0.f);
                        v1 = fmaxf(pv.y + v1, 0.f);
                    }
                    float2 r; r.x = v0; r.y = v1;
                    *(float2*)&OUTp[o] = r;
                }
            }
        }
    }
}

// ---------------- global-feature concat ----------------
__global__ void glob_copy(const float* __restrict__ g, float* __restrict__ out) {
    int idx = blockIdx.x * 256 + threadIdx.x;
    if (idx >= NM * 32) return;
    int mol = idx >> 5, j4 = idx & 31;
    float4 v = ((const float4*)g)[mol * 32 + j4];
    *(float4*)&out[(size_t)mol * OUTC + 300 + 4 * j4] = v;
}

// ---------------- launch ----------------
extern "C" void kernel_launch(void* const* d_in, const int* in_sizes, int n_in,
                              void* d_out, int out_size) {
    const float* atom_features   = (const float*)d_in[0];
    const float* f_ini           = (const float*)d_in[1];
    const float* global_features = (const float*)d_in[2];
    const float* W_i             = (const float*)d_in[3];
    const float* W_h             = (const float*)d_in[4];
    const float* W_o             = (const float*)d_in[5];
    const float* b_o             = (const float*)d_in[6];
    const int*   a2ib            = (const int*)d_in[7];
    const int*   mapping         = (const int*)d_in[8];
    float* out = (float*)d_out;

    static bool cfg = false;
    if (!cfg) {
        cudaFuncSetAttribute(mm_tf32<1, KP1>, cudaFuncAttributeMaxDynamicSharedMemorySize, SMTOT);
        cudaFuncSetAttribute(mm_tf32<2, KP2>, cudaFuncAttributeMaxDynamicSharedMemorySize, SMTOT);
        cudaFuncSetAttribute(mm_tf32<3, KP3>, cudaFuncAttributeMaxDynamicSharedMemorySize, SMTOT);
        cfg = true;
    }

    glob_copy<<<(NM * 32 + 255) / 256, 256>>>(global_features, out);
    prep_all<<<(320 * (KP1 + KP2 + KP3) + 255) / 256, 256>>>(W_i, W_h, W_o);

    // 1) inp = f_ini @ W_i           [pad fused into A producer]
    mm_tf32<1, KP1><<<NB / 64, 256, SMTOT>>>(f_ini, nullptr, nullptr, nullptr);
    // 2) m1 = sum relu(inp[mapping])
    gather_relu<<<(NB * 75 + 255) / 256, 256>>>(mapping);
    // 3+4) h2 = relu(inp + (sum m1[mapping]) @ W_h)   [gather fused, coalesced]
    mm_tf32<2, KP2><<<NB / 64, 256, SMTOT>>>(nullptr, mapping, nullptr, nullptr);
    // 5+6+7) out = mean(relu([atomF | sum h2[a2ib]] @ W_o + b_o))  [all fused]
    mm_tf32<3, KP3><<<NA / 64, 256, SMTOT>>>(atom_features, a2ib, b_o, out);
}

// round 7
// speedup vs baseline: 1.7101x; 1.5464x over previous
#include <cuda_runtime.h>
#include <cstdint>

#define NB 131072
#define NA 65536
#define NM 2048
#define DH 300
#define AF 133
#define K1 147
#define GF 128
#define OUTC 428

#define KP1 160
#define KP2 320
#define KP3 448

// ---------------- device scratch ----------------
__device__ __align__(16) float g_W1[320 * KP1];
__device__ __align__(16) float g_W2[320 * KP2];
__device__ __align__(16) float g_W3[320 * KP3];
__device__ __align__(16) float g_inp [(size_t)NB * DH];
__device__ __align__(16) float g_m1  [(size_t)NB * DH];
__device__ __align__(16) float g_m2  [(size_t)NB * KP2];   // padded cols 300..319 stay 0
__device__ __align__(16) float g_h2  [(size_t)NB * DH];
__device__ __align__(16) float g_msgs[(size_t)NA * DH];

// ---------------- helpers ----------------
__device__ __forceinline__ uint32_t s2u(const void* p) {
    uint32_t a;
    asm("{ .reg .u64 t; cvta.to.shared.u64 t, %1; cvt.u32.u64 %0, t; }"
        : "=r"(a) : "l"(p));
    return a;
}
__device__ __forceinline__ void cpa16(uint32_t s, const void* g) {
    asm volatile("cp.async.cg.shared.global [%0], [%1], 16;" :: "r"(s), "l"(g));
}
#define CP_COMMIT() asm volatile("cp.async.commit_group;" ::: "memory")
#define CP_WAIT1()  asm volatile("cp.async.wait_group 1;" ::: "memory")

__device__ __forceinline__ float rtf32(float x) {
    uint32_t u;
    asm("cvt.rna.tf32.f32 %0, %1;" : "=r"(u) : "f"(x));
    return __uint_as_float(u);
}
__device__ __forceinline__ void mma_tf32(float* c, const float* a, const float* b) {
    asm volatile(
        "mma.sync.aligned.m16n8k8.row.col.f32.tf32.tf32.f32 "
        "{%0,%1,%2,%3}, {%4,%5,%6,%7}, {%8,%9}, {%0,%1,%2,%3};"
        : "+f"(c[0]), "+f"(c[1]), "+f"(c[2]), "+f"(c[3])
        : "r"(__float_as_uint(a[0])), "r"(__float_as_uint(a[1])),
          "r"(__float_as_uint(a[2])), "r"(__float_as_uint(a[3])),
          "r"(__float_as_uint(b[0])), "r"(__float_as_uint(b[1])));
}

// ---------------- weight prep (one launch for all 3) ----------------
__global__ void prep_all(const float* __restrict__ W1s,
                         const float* __restrict__ W2s,
                         const float* __restrict__ W3s) {
    int idx = blockIdx.x * 256 + threadIdx.x;
    const int T1 = 320 * KP1, T2 = 320 * KP2;
    const float* W;
    float* B;
    int KP, mode;
    if (idx < T1) { W = W1s; B = g_W1; KP = KP1; mode = 1; }
    else if (idx < T1 + T2) { idx -= T1; W = W2s; B = g_W2; KP = KP2; mode = 2; }
    else {
        idx -= T1 + T2;
        if (idx >= 320 * KP3) return;
        W = W3s; B = g_W3; KP = KP3; mode = 3;
    }
    int n = idx / KP, k = idx % KP;
    int src;
    if (mode == 3) src = (k < 133) ? k : (k >= 136 && k < 436) ? k - 3 : -1;
    else if (mode == 1) src = (k < K1) ? k : -1;
    else src = (k < DH) ? k : -1;
    float v = (n < 300 && src >= 0) ? W[src * 300 + n] : 0.f;
    B[(size_t)n * KP + k] = rtf32(v);
}

// ---------------- gather1: m1 = sum_j relu(inp[map[j]]) ----------------
__global__ void gather_relu(const int* __restrict__ map) {
    int idx = blockIdx.x * 256 + threadIdx.x;
    if (idx >= NB * 75) return;
    int r = idx / 75, c = idx % 75;
    int4 m = ((const int4*)map)[r];
    const float4* S = (const float4*)g_inp;
    float4 a = S[(size_t)m.x * 75 + c];
    float4 b = S[(size_t)m.y * 75 + c];
    float4 cc = S[(size_t)m.z * 75 + c];
    float4 d = S[(size_t)m.w * 75 + c];
    float4 o;
    o.x = fmaxf(a.x, 0.f) + fmaxf(b.x, 0.f) + fmaxf(cc.x, 0.f) + fmaxf(d.x, 0.f);
    o.y = fmaxf(a.y, 0.f) + fmaxf(b.y, 0.f) + fmaxf(cc.y, 0.f) + fmaxf(d.y, 0.f);
    o.z = fmaxf(a.z, 0.f) + fmaxf(b.z, 0.f) + fmaxf(cc.z, 0.f) + fmaxf(d.z, 0.f);
    o.w = fmaxf(a.w, 0.f) + fmaxf(b.w, 0.f) + fmaxf(cc.w, 0.f) + fmaxf(d.w, 0.f);
    ((float4*)g_m1)[(size_t)r * 75 + c] = o;
}

// ---------------- gather2: m2 = tf32(sum_j m1[map[j]]) -> padded [NB x 320] ----------------
__global__ void gather2(const int* __restrict__ map) {
    int idx = blockIdx.x * 256 + threadIdx.x;
    if (idx >= NB * 75) return;
    int r = idx / 75, c = idx % 75;
    int4 m = ((const int4*)map)[r];
    const float4* S = (const float4*)g_m1;
    float4 a = S[(size_t)m.x * 75 + c];
    float4 b = S[(size_t)m.y * 75 + c];
    float4 cc = S[(size_t)m.z * 75 + c];
    float4 d = S[(size_t)m.w * 75 + c];
    float4 o;
    o.x = rtf32(a.x + b.x + cc.x + d.x);
    o.y = rtf32(a.y + b.y + cc.y + d.y);
    o.z = rtf32(a.z + b.z + cc.z + d.z);
    o.w = rtf32(a.w + b.w + cc.w + d.w);
    *(float4*)&g_m2[(size_t)r * KP2 + c * 4] = o;
}

// ---------------- gather_atom: msgs = tf32(sum_j h2[a2ib[j]]) -> [NA x 300] ----------------
__global__ void gather_atom(const int* __restrict__ a2ib) {
    int idx = blockIdx.x * 256 + threadIdx.x;
    if (idx >= NA * 75) return;
    int r = idx / 75, c = idx % 75;
    int4 m = ((const int4*)a2ib)[r];
    const float4* S = (const float4*)g_h2;
    float4 a = S[(size_t)m.x * 75 + c];
    float4 b = S[(size_t)m.y * 75 + c];
    float4 cc = S[(size_t)m.z * 75 + c];
    float4 d = S[(size_t)m.w * 75 + c];
    float4 o;
    o.x = rtf32(a.x + b.x + cc.x + d.x);
    o.y = rtf32(a.y + b.y + cc.y + d.y);
    o.z = rtf32(a.z + b.z + cc.z + d.z);
    o.w = rtf32(a.w + b.w + cc.w + d.w);
    ((float4*)g_msgs)[(size_t)r * 75 + c] = o;
}

// ---------------- TF32 GEMM: BM=128, BN=320 (full), BK=32, 512 thr, 3 stages ----------------
// Warp grid 2(m) x 8(n); warp tile 64x40 (identical inner machinery to the R4 champion).
// MODE 1: A <- f_ini via LDG+rtf32 (pad fused)       -> g_inp
// MODE 2: A <- g_m2 via cp.async (pre-rounded)       -> g_h2 = relu(g_inp + C)
// MODE 3: A <- [atomF | g_msgs | 0] via LDG          -> fused mean readout to out
#define BOFF  18432                 // A: 128*144
#define STG   (BOFF + 320 * 144)    // + B: 46080 -> 64512
#define SMTOT (3 * STG)             // 193536

template <int MODE, int KP>
__global__ void __launch_bounds__(512)
mm_tf32(const float* __restrict__ srcA,
        const float* __restrict__ bias, float* __restrict__ dOut) {
    constexpr int NCH = KP / 32;
    const float* __restrict__ Wt = (MODE == 1) ? g_W1 : (MODE == 2) ? g_W2 : g_W3;

    extern __shared__ __align__(16) char smem[];
    const uint32_t sb = s2u(smem);
    const int tid = threadIdx.x, w = tid >> 5, lane = tid & 31;
    const int wr = w & 1, wc = w >> 1;       // warp tile 64x40
    const int rowBase = blockIdx.x * 128;

    float acc[4][5][4];
#pragma unroll
    for (int i = 0; i < 4; i++)
#pragma unroll
        for (int j = 0; j < 5; j++)
#pragma unroll
            for (int q = 0; q < 4; q++) acc[i][j][q] = 0.f;

    // ---- A producer (MODE 1/3): warp owns 8 rows, lane owns one k column ----
    float rbuf[8];
    auto loadA_regs = [&](int c) {
        const int k = c * 32 + lane;
#pragma unroll
        for (int i = 0; i < 8; i++) {
            const int grow = rowBase + w * 8 + i;
            float v = 0.f;
            if (MODE == 1) {
                if (k < K1) v = rtf32(srcA[(size_t)grow * K1 + k]);
            } else if (MODE == 3) {
                if (k < AF) v = rtf32(srcA[(size_t)grow * AF + k]);
                else if (k >= 136 && k < 436) v = g_msgs[(size_t)grow * DH + (k - 136)];
            }
            rbuf[i] = v;
        }
    };
    auto stsA = [&](int st) {
        char* p = smem + st * STG + (w * 8) * 144 + lane * 4;
#pragma unroll
        for (int i = 0; i < 8; i++) *(float*)(p + i * 144) = rbuf[i];
    };

    // ---- A via cp.async (MODE 2) ----
    const int lrow = tid >> 3, lseg = tid & 7;   // lrow 0..63
    auto cpA = [&](int c, int st) {
#pragma unroll
        for (int it = 0; it < 2; it++) {
            int row = lrow + it * 64;
            cpa16(sb + st * STG + row * 144 + lseg * 16,
                  g_m2 + (size_t)(rowBase + row) * KP2 + c * 32 + lseg * 4);
        }
    };
    auto loadB = [&](int c, int st) {
#pragma unroll
        for (int it = 0; it < 5; it++) {
            int row = lrow + it * 64;
            cpa16(sb + st * STG + BOFF + row * 144 + lseg * 16,
                  Wt + (size_t)row * KP + c * 32 + lseg * 4);
        }
    };

    // ---- prologue: fill stages 0,1; stage-2 regs in flight ----
    if (MODE != 2) {
        loadA_regs(0); stsA(0); loadB(0, 0); CP_COMMIT();
        loadA_regs(1); stsA(1); loadB(1, 1); CP_COMMIT();
        loadA_regs(2);
    } else {
        cpA(0, 0); loadB(0, 0); CP_COMMIT();
        cpA(1, 1); loadB(1, 1); CP_COMMIT();
    }

    const uint32_t aBase = (wr * 64 + (lane >> 2)) * 144 + (lane & 3) * 4;
    const uint32_t bBase = BOFF + (wc * 40 + (lane >> 2)) * 144 + (lane & 3) * 4;

    for (int c = 0; c < NCH; c++) {
        CP_WAIT1();
        __syncthreads();
        if (c + 2 < NCH) {
            const int st = (c + 2) % 3;
            if (MODE != 2) { stsA(st); }
            else          { cpA(c + 2, st); }
            loadB(c + 2, st);
        }
        CP_COMMIT();
        if (MODE != 2 && c + 3 < NCH) loadA_regs(c + 3);

        const char* stp = smem + (c % 3) * STG;
#pragma unroll
        for (int k8 = 0; k8 < 4; k8++) {
            float af[4][4], bfr[5][2];
#pragma unroll
            for (int mt = 0; mt < 4; mt++) {
                const char* p = stp + aBase + mt * (16 * 144) + k8 * 32;
                af[mt][0] = *(const float*)p;
                af[mt][1] = *(const float*)(p + 8 * 144);
                af[mt][2] = *(const float*)(p + 16);
                af[mt][3] = *(const float*)(p + 8 * 144 + 16);
            }
#pragma unroll
            for (int nt = 0; nt < 5; nt++) {
                const char* p = stp + bBase + nt * (8 * 144) + k8 * 32;
                bfr[nt][0] = *(const float*)p;
                bfr[nt][1] = *(const float*)(p + 16);
            }
#pragma unroll
            for (int mt = 0; mt < 4; mt++)
#pragma unroll
                for (int nt = 0; nt < 5; nt++)
                    mma_tf32(acc[mt][nt], af[mt], bfr[nt]);
        }
    }

    if (MODE == 3) {
        // fused per-molecule mean readout: 128 rows = 4 molecules
        const int molBase = blockIdx.x * 4 + wr * 2;
#pragma unroll
        for (int mtb = 0; mtb < 4; mtb += 2) {
#pragma unroll
            for (int nt = 0; nt < 5; nt++) {
                const int col2 = wc * 40 + nt * 8 + (lane & 3) * 2;
                float b0 = 0.f, b1 = 0.f;
                if (col2 < DH) { b0 = bias[col2]; b1 = bias[col2 + 1]; }
                float s0 = 0.f, s1 = 0.f;
#pragma unroll
                for (int p = 0; p < 2; p++) {
#pragma unroll
                    for (int h = 0; h < 2; h++) {
                        s0 += fmaxf(acc[mtb + p][nt][h * 2]     + b0, 0.f);
                        s1 += fmaxf(acc[mtb + p][nt][h * 2 + 1] + b1, 0.f);
                    }
                }
#pragma unroll
                for (int off = 16; off >= 4; off >>= 1) {
                    s0 += __shfl_down_sync(0xFFFFFFFFu, s0, off);
                    s1 += __shfl_down_sync(0xFFFFFFFFu, s1, off);
                }
                if (lane < 4) {
                    const int colw = wc * 40 + nt * 8 + lane * 2;
                    if (colw < DH) {
                        const int mol = molBase + (mtb >> 1);
                        float2 v;
                        v.x = s0 * 0.03125f;
                        v.y = s1 * 0.03125f;
                        *(float2*)&dOut[(size_t)mol * OUTC + colw] = v;
                    }
                }
            }
        }
    } else {
        float* __restrict__ OUTp = (MODE == 1) ? g_inp : g_h2;
        const int crow = lane >> 2, cc0 = (lane & 3) * 2;
#pragma unroll
        for (int mt = 0; mt < 4; mt++) {
#pragma unroll
            for (int nt = 0; nt < 5; nt++) {
                const int col = wc * 40 + nt * 8 + cc0;
                if (col >= DH) continue;
#pragma unroll
                for (int half = 0; half < 2; half++) {
                    const int grow = rowBase + wr * 64 + mt * 16 + crow + half * 8;
                    const size_t o = (size_t)grow * DH + col;
                    float v0 = acc[mt][nt][half * 2];
                    float v1 = acc[mt][nt][half * 2 + 1];
                    if (MODE == 2) {
                        float2 pv = *(const float2*)&g_inp[o];
                        v0 = fmaxf(pv.x + v0, 0.f);
                        v1 = fmaxf(pv.y + v1, 0.f);
                    }
                    float2 r; r.x = v0; r.y = v1;
                    *(float2*)&OUTp[o] = r;
                }
            }
        }
    }
}

// ---------------- global-feature concat ----------------
__global__ void glob_copy(const float* __restrict__ g, float* __restrict__ out) {
    int idx = blockIdx.x * 256 + threadIdx.x;
    if (idx >= NM * 32) return;
    int mol = idx >> 5, j4 = idx & 31;
    float4 v = ((const float4*)g)[mol * 32 + j4];
    *(float4*)&out[(size_t)mol * OUTC + 300 + 4 * j4] = v;
}

// ---------------- launch ----------------
extern "C" void kernel_launch(void* const* d_in, const int* in_sizes, int n_in,
                              void* d_out, int out_size) {
    const float* atom_features   = (const float*)d_in[0];
    const float* f_ini           = (const float*)d_in[1];
    const float* global_features = (const float*)d_in[2];
    const float* W_i             = (const float*)d_in[3];
    const float* W_h             = (const float*)d_in[4];
    const float* W_o             = (const float*)d_in[5];
    const float* b_o             = (const float*)d_in[6];
    const int*   a2ib            = (const int*)d_in[7];
    const int*   mapping         = (const int*)d_in[8];
    float* out = (float*)d_out;

    static bool cfg = false;
    if (!cfg) {
        cudaFuncSetAttribute(mm_tf32<1, KP1>, cudaFuncAttributeMaxDynamicSharedMemorySize, SMTOT);
        cudaFuncSetAttribute(mm_tf32<2, KP2>, cudaFuncAttributeMaxDynamicSharedMemorySize, SMTOT);
        cudaFuncSetAttribute(mm_tf32<3, KP3>, cudaFuncAttributeMaxDynamicSharedMemorySize, SMTOT);
        cfg = true;
    }

    glob_copy<<<(NM * 32 + 255) / 256, 256>>>(global_features, out);
    prep_all<<<(320 * (KP1 + KP2 + KP3) + 255) / 256, 256>>>(W_i, W_h, W_o);

    // 1) inp = f_ini @ W_i               [pad fused into A producer]
    mm_tf32<1, KP1><<<NB / 128, 512, SMTOT>>>(f_ini, nullptr, nullptr);
    // 2) m1 = sum relu(inp[mapping])
    gather_relu<<<(NB * 75 + 255) / 256, 256>>>(mapping);
    // 3) m2 = tf32(sum m1[mapping])
    gather2<<<(NB * 75 + 255) / 256, 256>>>(mapping);
    // 4) h2 = relu(inp + m2 @ W_h)
    mm_tf32<2, KP2><<<NB / 128, 512, SMTOT>>>(nullptr, nullptr, nullptr);
    // 5) msgs = tf32(sum h2[a2ib])
    gather_atom<<<(NA * 75 + 255) / 256, 256>>>(a2ib);
    // 6+7) out = mean(relu([atomF | msgs] @ W_o + b_o))   [readout fused]
    mm_tf32<3, KP3><<<NA / 128, 512, SMTOT>>>(atom_features, b_o, out);
}

// round 8
// speedup vs baseline: 1.7533x; 1.0252x over previous
#include <cuda_runtime.h>
#include <cstdint>

#define NB 131072
#define NA 65536
#define NM 2048
#define DH 300
#define AF 133
#define K1 147
#define GF 128
#define OUTC 428

#define KP1 160
#define KP2 320
#define KP3 448

// ---------------- device scratch ----------------
__device__ __align__(16) float g_W1[320 * KP1];
__device__ __align__(16) float g_W2[320 * KP2];
__device__ __align__(16) float g_W3[320 * KP3];
__device__ __align__(16) float g_inp [(size_t)NB * DH];
__device__ __align__(16) float g_m1  [(size_t)NB * DH];
__device__ __align__(16) float g_m2  [(size_t)NB * KP2];   // padded cols 300..319 stay 0
__device__ __align__(16) float g_h2  [(size_t)NB * DH];
__device__ __align__(16) float g_msgs[(size_t)NA * DH];

// ---------------- helpers ----------------
__device__ __forceinline__ uint32_t s2u(const void* p) {
    uint32_t a;
    asm("{ .reg .u64 t; cvta.to.shared.u64 t, %1; cvt.u32.u64 %0, t; }"
        : "=r"(a) : "l"(p));
    return a;
}
__device__ __forceinline__ void cpa16(uint32_t s, const void* g) {
    asm volatile("cp.async.cg.shared.global [%0], [%1], 16;" :: "r"(s), "l"(g));
}
#define CP_COMMIT() asm volatile("cp.async.commit_group;" ::: "memory")
#define CP_WAIT1()  asm volatile("cp.async.wait_group 1;" ::: "memory")

__device__ __forceinline__ float rtf32(float x) {
    uint32_t u;
    asm("cvt.rna.tf32.f32 %0, %1;" : "=r"(u) : "f"(x));
    return __uint_as_float(u);
}
// ldmatrix b16 used to fetch tf32 fragments (CUTLASS-style):
// an 8x8 f32 tile = two m8n8 b16 tiles (16B column halves).
__device__ __forceinline__ void ldmx4(uint32_t* r, uint32_t a) {
    asm volatile("ldmatrix.sync.aligned.m8n8.x4.shared.b16 {%0,%1,%2,%3}, [%4];"
                 : "=r"(r[0]), "=r"(r[1]), "=r"(r[2]), "=r"(r[3]) : "r"(a));
}
__device__ __forceinline__ void ldmx2(uint32_t* r, uint32_t a) {
    asm volatile("ldmatrix.sync.aligned.m8n8.x2.shared.b16 {%0,%1}, [%2];"
                 : "=r"(r[0]), "=r"(r[1]) : "r"(a));
}
__device__ __forceinline__ void mma_tf32(float* c, const uint32_t* a, const uint32_t* b) {
    asm volatile(
        "mma.sync.aligned.m16n8k8.row.col.f32.tf32.tf32.f32 "
        "{%0,%1,%2,%3}, {%4,%5,%6,%7}, {%8,%9}, {%0,%1,%2,%3};"
        : "+f"(c[0]), "+f"(c[1]), "+f"(c[2]), "+f"(c[3])
        : "r"(a[0]), "r"(a[1]), "r"(a[2]), "r"(a[3]), "r"(b[0]), "r"(b[1]));
}

// ---------------- weight prep (one launch for all 3) ----------------
__global__ void prep_all(const float* __restrict__ W1s,
                         const float* __restrict__ W2s,
                         const float* __restrict__ W3s) {
    int idx = blockIdx.x * 256 + threadIdx.x;
    const int T1 = 320 * KP1, T2 = 320 * KP2;
    const float* W;
    float* B;
    int KP, mode;
    if (idx < T1) { W = W1s; B = g_W1; KP = KP1; mode = 1; }
    else if (idx < T1 + T2) { idx -= T1; W = W2s; B = g_W2; KP = KP2; mode = 2; }
    else {
        idx -= T1 + T2;
        if (idx >= 320 * KP3) return;
        W = W3s; B = g_W3; KP = KP3; mode = 3;
    }
    int n = idx / KP, k = idx % KP;
    int src;
    if (mode == 3) src = (k < 133) ? k : (k >= 136 && k < 436) ? k - 3 : -1;
    else if (mode == 1) src = (k < K1) ? k : -1;
    else src = (k < DH) ? k : -1;
    float v = (n < 300 && src >= 0) ? W[src * 300 + n] : 0.f;
    B[(size_t)n * KP + k] = rtf32(v);
}

// ---------------- gather1: m1 = sum_j relu(inp[map[j]]) ----------------
__global__ void gather_relu(const int* __restrict__ map) {
    int idx = blockIdx.x * 256 + threadIdx.x;
    if (idx >= NB * 75) return;
    int r = idx / 75, c = idx % 75;
    int4 m = ((const int4*)map)[r];
    const float4* S = (const float4*)g_inp;
    float4 a = S[(size_t)m.x * 75 + c];
    float4 b = S[(size_t)m.y * 75 + c];
    float4 cc = S[(size_t)m.z * 75 + c];
    float4 d = S[(size_t)m.w * 75 + c];
    float4 o;
    o.x = fmaxf(a.x, 0.f) + fmaxf(b.x, 0.f) + fmaxf(cc.x, 0.f) + fmaxf(d.x, 0.f);
    o.y = fmaxf(a.y, 0.f) + fmaxf(b.y, 0.f) + fmaxf(cc.y, 0.f) + fmaxf(d.y, 0.f);
    o.z = fmaxf(a.z, 0.f) + fmaxf(b.z, 0.f) + fmaxf(cc.z, 0.f) + fmaxf(d.z, 0.f);
    o.w = fmaxf(a.w, 0.f) + fmaxf(b.w, 0.f) + fmaxf(cc.w, 0.f) + fmaxf(d.w, 0.f);
    ((float4*)g_m1)[(size_t)r * 75 + c] = o;
}

// ---------------- gather2: m2 = tf32(sum_j m1[map[j]]) -> padded [NB x 320] ----------------
__global__ void gather2(const int* __restrict__ map) {
    int idx = blockIdx.x * 256 + threadIdx.x;
    if (idx >= NB * 75) return;
    int r = idx / 75, c = idx % 75;
    int4 m = ((const int4*)map)[r];
    const float4* S = (const float4*)g_m1;
    float4 a = S[(size_t)m.x * 75 + c];
    float4 b = S[(size_t)m.y * 75 + c];
    float4 cc = S[(size_t)m.z * 75 + c];
    float4 d = S[(size_t)m.w * 75 + c];
    float4 o;
    o.x = rtf32(a.x + b.x + cc.x + d.x);
    o.y = rtf32(a.y + b.y + cc.y + d.y);
    o.z = rtf32(a.z + b.z + cc.z + d.z);
    o.w = rtf32(a.w + b.w + cc.w + d.w);
    *(float4*)&g_m2[(size_t)r * KP2 + c * 4] = o;
}

// ---------------- gather_atom: msgs = tf32(sum_j h2[a2ib[j]]) -> [NA x 300] ----------------
__global__ void gather_atom(const int* __restrict__ a2ib) {
    int idx = blockIdx.x * 256 + threadIdx.x;
    if (idx >= NA * 75) return;
    int r = idx / 75, c = idx % 75;
    int4 m = ((const int4*)a2ib)[r];
    const float4* S = (const float4*)g_h2;
    float4 a = S[(size_t)m.x * 75 + c];
    float4 b = S[(size_t)m.y * 75 + c];
    float4 cc = S[(size_t)m.z * 75 + c];
    float4 d = S[(size_t)m.w * 75 + c];
    float4 o;
    o.x = rtf32(a.x + b.x + cc.x + d.x);
    o.y = rtf32(a.y + b.y + cc.y + d.y);
    o.z = rtf32(a.z + b.z + cc.z + d.z);
    o.w = rtf32(a.w + b.w + cc.w + d.w);
    ((float4*)g_msgs)[(size_t)r * 75 + c] = o;
}

// ---------------- TF32 GEMM: BM=128, BN=320, BK=32, 512 thr, 3 stages ----------------
// Warp grid 2(m) x 8(n); warp tile 64x40. Fragments fetched via ldmatrix.b16.
#define BOFF  18432                 // A: 128*144
#define STG   (BOFF + 320 * 144)    // + B: 46080 -> 64512
#define SMTOT (3 * STG)             // 193536

template <int MODE, int KP>
__global__ void __launch_bounds__(512)
mm_tf32(const float* __restrict__ srcA,
        const float* __restrict__ bias, float* __restrict__ dOut) {
    constexpr int NCH = KP / 32;
    const float* __restrict__ Wt = (MODE == 1) ? g_W1 : (MODE == 2) ? g_W2 : g_W3;

    extern __shared__ __align__(16) char smem[];
    const uint32_t sb = s2u(smem);
    const int tid = threadIdx.x, w = tid >> 5, lane = tid & 31;
    const int wr = w & 1, wc = w >> 1;       // warp tile 64x40
    const int rowBase = blockIdx.x * 128;

    float acc[4][5][4];
#pragma unroll
    for (int i = 0; i < 4; i++)
#pragma unroll
        for (int j = 0; j < 5; j++)
#pragma unroll
            for (int q = 0; q < 4; q++) acc[i][j][q] = 0.f;

    // ---- A producer (MODE 1/3): warp owns 8 rows, lane owns one k column ----
    float rbuf[8];
    auto loadA_regs = [&](int c) {
        const int k = c * 32 + lane;
#pragma unroll
        for (int i = 0; i < 8; i++) {
            const int grow = rowBase + w * 8 + i;
            float v = 0.f;
            if (MODE == 1) {
                if (k < K1) v = rtf32(srcA[(size_t)grow * K1 + k]);
            } else if (MODE == 3) {
                if (k < AF) v = rtf32(srcA[(size_t)grow * AF + k]);
                else if (k >= 136 && k < 436) v = g_msgs[(size_t)grow * DH + (k - 136)];
            }
            rbuf[i] = v;
        }
    };
    auto stsA = [&](int st) {
        char* p = smem + st * STG + (w * 8) * 144 + lane * 4;
#pragma unroll
        for (int i = 0; i < 8; i++) *(float*)(p + i * 144) = rbuf[i];
    };

    // ---- A via cp.async (MODE 2) ----
    const int lrow = tid >> 3, lseg = tid & 7;   // lrow 0..63
    auto cpA = [&](int c, int st) {
#pragma unroll
        for (int it = 0; it < 2; it++) {
            int row = lrow + it * 64;
            cpa16(sb + st * STG + row * 144 + lseg * 16,
                  g_m2 + (size_t)(rowBase + row) * KP2 + c * 32 + lseg * 4);
        }
    };
    auto loadB = [&](int c, int st) {
#pragma unroll
        for (int it = 0; it < 5; it++) {
            int row = lrow + it * 64;
            cpa16(sb + st * STG + BOFF + row * 144 + lseg * 16,
                  Wt + (size_t)row * KP + c * 32 + lseg * 4);
        }
    };

    // ---- prologue ----
    if (MODE != 2) {
        loadA_regs(0); stsA(0); loadB(0, 0); CP_COMMIT();
        loadA_regs(1); stsA(1); loadB(1, 1); CP_COMMIT();
        loadA_regs(2);
    } else {
        cpA(0, 0); loadB(0, 0); CP_COMMIT();
        cpA(1, 1); loadB(1, 1); CP_COMMIT();
    }

    // ldmatrix per-thread address bases.
    // A x4 tiles: {r0-7/h0, r8-15/h0, r0-7/h1, r8-15/h1} -> frag {a0,a1,a2,a3}
    const uint32_t aOff = (uint32_t)(wr * 64 + ((lane >> 3) & 1) * 8 + (lane & 7)) * 144
                        + (uint32_t)(lane >> 4) * 16;
    // B x2 tiles: {n0-7/k0-3, n0-7/k4-7} -> frag {b0,b1}; threads>=16 mirror 0-15
    const int bl = lane & 15;
    const uint32_t bOff = BOFF + (uint32_t)(wc * 40 + (bl & 7)) * 144
                        + (uint32_t)(bl >> 3) * 16;

    for (int c = 0; c < NCH; c++) {
        CP_WAIT1();
        __syncthreads();
        if (c + 2 < NCH) {
            const int st = (c + 2) % 3;
            if (MODE != 2) { stsA(st); }
            else          { cpA(c + 2, st); }
            loadB(c + 2, st);
        }
        CP_COMMIT();
        if (MODE != 2 && c + 3 < NCH) loadA_regs(c + 3);

        const uint32_t stp = sb + (c % 3) * STG;
#pragma unroll
        for (int k8 = 0; k8 < 4; k8++) {
            uint32_t af[4][4], bf[5][2];
#pragma unroll
            for (int mt = 0; mt < 4; mt++)
                ldmx4(af[mt], stp + aOff + mt * (16 * 144) + k8 * 32);
#pragma unroll
            for (int nt = 0; nt < 5; nt++)
                ldmx2(bf[nt], stp + bOff + nt * (8 * 144) + k8 * 32);
#pragma unroll
            for (int mt = 0; mt < 4; mt++)
#pragma unroll
                for (int nt = 0; nt < 5; nt++)
                    mma_tf32(acc[mt][nt], af[mt], bf[nt]);
        }
    }

    if (MODE == 3) {
        // fused per-molecule mean readout: 128 rows = 4 molecules
        const int molBase = blockIdx.x * 4 + wr * 2;
#pragma unroll
        for (int mtb = 0; mtb < 4; mtb += 2) {
#pragma unroll
            for (int nt = 0; nt < 5; nt++) {
                const int col2 = wc * 40 + nt * 8 + (lane & 3) * 2;
                float b0 = 0.f, b1 = 0.f;
                if (col2 < DH) { b0 = bias[col2]; b1 = bias[col2 + 1]; }
                float s0 = 0.f, s1 = 0.f;
#pragma unroll
                for (int p = 0; p < 2; p++) {
#pragma unroll
                    for (int h = 0; h < 2; h++) {
                        s0 += fmaxf(acc[mtb + p][nt][h * 2]     + b0, 0.f);
                        s1 += fmaxf(acc[mtb + p][nt][h * 2 + 1] + b1, 0.f);
                    }
                }
#pragma unroll
                for (int off = 16; off >= 4; off >>= 1) {
                    s0 += __shfl_down_sync(0xFFFFFFFFu, s0, off);
                    s1 += __shfl_down_sync(0xFFFFFFFFu, s1, off);
                }
                if (lane < 4) {
                    const int colw = wc * 40 + nt * 8 + lane * 2;
                    if (colw < DH) {
                        const int mol = molBase + (mtb >> 1);
                        float2 v;
                        v.x = s0 * 0.03125f;
                        v.y = s1 * 0.03125f;
                        *(float2*)&dOut[(size_t)mol * OUTC + colw] = v;
                    }
                }
            }
        }
    } else {
        float* __restrict__ OUTp = (MODE == 1) ? g_inp : g_h2;
        const int crow = lane >> 2, cc0 = (lane & 3) * 2;
#pragma unroll
        for (int mt = 0; mt < 4; mt++) {
#pragma unroll
            for (int nt = 0; nt < 5; nt++) {
                const int col = wc * 40 + nt * 8 + cc0;
                if (col >= DH) continue;
#pragma unroll
                for (int half = 0; half < 2; half++) {
                    const int grow = rowBase + wr * 64 + mt * 16 + crow + half * 8;
                    const size_t o = (size_t)grow * DH + col;
                    float v0 = acc[mt][nt][half * 2];
                    float v1 = acc[mt][nt][half * 2 + 1];
                    if (MODE == 2) {
                        float2 pv = *(const float2*)&g_inp[o];
                        v0 = fmaxf(pv.x + v0, 0.f);
                        v1 = fmaxf(pv.y + v1, 0.f);
                    }
                    float2 r; r.x = v0; r.y = v1;
                    *(float2*)&OUTp[o] = r;
                }
            }
        }
    }
}

// ---------------- global-feature concat ----------------
__global__ void glob_copy(const float* __restrict__ g, float* __restrict__ out) {
    int idx = blockIdx.x * 256 + threadIdx.x;
    if (idx >= NM * 32) return;
    int mol = idx >> 5, j4 = idx & 31;
    float4 v = ((const float4*)g)[mol * 32 + j4];
    *(float4*)&out[(size_t)mol * OUTC + 300 + 4 * j4] = v;
}

// ---------------- launch ----------------
extern "C" void kernel_launch(void* const* d_in, const int* in_sizes, int n_in,
                              void* d_out, int out_size) {
    const float* atom_features   = (const float*)d_in[0];
    const float* f_ini           = (const float*)d_in[1];
    const float* global_features = (const float*)d_in[2];
    const float* W_i             = (const float*)d_in[3];
    const float* W_h             = (const float*)d_in[4];
    const float* W_o             = (const float*)d_in[5];
    const float* b_o             = (const float*)d_in[6];
    const int*   a2ib            = (const int*)d_in[7];
    const int*   mapping         = (const int*)d_in[8];
    float* out = (float*)d_out;

    static bool cfg = false;
    if (!cfg) {
        cudaFuncSetAttribute(mm_tf32<1, KP1>, cudaFuncAttributeMaxDynamicSharedMemorySize, SMTOT);
        cudaFuncSetAttribute(mm_tf32<2, KP2>, cudaFuncAttributeMaxDynamicSharedMemorySize, SMTOT);
        cudaFuncSetAttribute(mm_tf32<3, KP3>, cudaFuncAttributeMaxDynamicSharedMemorySize, SMTOT);
        cfg = true;
    }

    glob_copy<<<(NM * 32 + 255) / 256, 256>>>(global_features, out);
    prep_all<<<(320 * (KP1 + KP2 + KP3) + 255) / 256, 256>>>(W_i, W_h, W_o);

    // 1) inp = f_ini @ W_i               [pad fused into A producer]
    mm_tf32<1, KP1><<<NB / 128, 512, SMTOT>>>(f_ini, nullptr, nullptr);
    // 2) m1 = sum relu(inp[mapping])
    gather_relu<<<(NB * 75 + 255) / 256, 256>>>(mapping);
    // 3) m2 = tf32(sum m1[mapping])
    gather2<<<(NB * 75 + 255) / 256, 256>>>(mapping);
    // 4) h2 = relu(inp + m2 @ W_h)
    mm_tf32<2, KP2><<<NB / 128, 512, SMTOT>>>(nullptr, nullptr, nullptr);
    // 5) msgs = tf32(sum h2[a2ib])
    gather_atom<<<(NA * 75 + 255) / 256, 256>>>(a2ib);
    // 6+7) out = mean(relu([atomF | msgs] @ W_o + b_o))   [readout fused]
    mm_tf32<3, KP3><<<NA / 128, 512, SMTOT>>>(atom_features, b_o, out);
}

// round 9
// speedup vs baseline: 2.2300x; 1.2719x over previous
#include <cuda_runtime.h>
#include <cuda_fp16.h>
#include <cstdint>

#define NB 131072
#define NA 65536
#define NM 2048
#define DH 300
#define AF 133
#define K1 147
#define GF 128
#define OUTC 428

#define KP1 160
#define KP2 320
#define KP3 448

// ---------------- device scratch ----------------
__device__ __align__(16) __half g_W1[320 * KP1];
__device__ __align__(16) __half g_W2[320 * KP2];
__device__ __align__(16) __half g_W3[320 * KP3];
__device__ __align__(16) float  g_inp [(size_t)NB * DH];
__device__ __align__(16) float  g_m1  [(size_t)NB * DH];
__device__ __align__(16) __half g_m2h [(size_t)NB * KP2];   // cols 300..319 stay 0
__device__ __align__(16) float  g_h2  [(size_t)NB * DH];
__device__ __align__(16) __half g_msgsh[(size_t)NA * DH];

// ---------------- helpers ----------------
__device__ __forceinline__ uint32_t s2u(const void* p) {
    uint32_t a;
    asm("{ .reg .u64 t; cvta.to.shared.u64 t, %1; cvt.u32.u64 %0, t; }"
        : "=r"(a) : "l"(p));
    return a;
}
__device__ __forceinline__ void cpa16(uint32_t s, const void* g) {
    asm volatile("cp.async.cg.shared.global [%0], [%1], 16;" :: "r"(s), "l"(g));
}
#define CP_COMMIT() asm volatile("cp.async.commit_group;" ::: "memory")
#define CP_WAIT1()  asm volatile("cp.async.wait_group 1;" ::: "memory")

__device__ __forceinline__ void ldmx4(uint32_t* r, uint32_t a) {
    asm volatile("ldmatrix.sync.aligned.m8n8.x4.shared.b16 {%0,%1,%2,%3}, [%4];"
                 : "=r"(r[0]), "=r"(r[1]), "=r"(r[2]), "=r"(r[3]) : "r"(a));
}
__device__ __forceinline__ void ldmx2(uint32_t* r, uint32_t a) {
    asm volatile("ldmatrix.sync.aligned.m8n8.x2.shared.b16 {%0,%1}, [%2];"
                 : "=r"(r[0]), "=r"(r[1]) : "r"(a));
}
__device__ __forceinline__ void mma_f16(float* c, const uint32_t* a, const uint32_t* b) {
    asm volatile(
        "mma.sync.aligned.m16n8k16.row.col.f32.f16.f16.f32 "
        "{%0,%1,%2,%3}, {%4,%5,%6,%7}, {%8,%9}, {%0,%1,%2,%3};"
        : "+f"(c[0]), "+f"(c[1]), "+f"(c[2]), "+f"(c[3])
        : "r"(a[0]), "r"(a[1]), "r"(a[2]), "r"(a[3]), "r"(b[0]), "r"(b[1]));
}

// ---------------- weight prep (one launch for all 3) ----------------
__global__ void prep_all(const float* __restrict__ W1s,
                         const float* __restrict__ W2s,
                         const float* __restrict__ W3s) {
    int idx = blockIdx.x * 256 + threadIdx.x;
    const int T1 = 320 * KP1, T2 = 320 * KP2;
    const float* W;
    __half* B;
    int KP, mode;
    if (idx < T1) { W = W1s; B = g_W1; KP = KP1; mode = 1; }
    else if (idx < T1 + T2) { idx -= T1; W = W2s; B = g_W2; KP = KP2; mode = 2; }
    else {
        idx -= T1 + T2;
        if (idx >= 320 * KP3) return;
        W = W3s; B = g_W3; KP = KP3; mode = 3;
    }
    int n = idx / KP, k = idx % KP;
    int src;
    if (mode == 3) src = (k < 133) ? k : (k >= 136 && k < 436) ? k - 3 : -1;
    else if (mode == 1) src = (k < K1) ? k : -1;
    else src = (k < DH) ? k : -1;
    float v = (n < 300 && src >= 0) ? W[src * 300 + n] : 0.f;
    B[(size_t)n * KP + k] = __float2half_rn(v);
}

// ---------------- gather1: m1 = sum_j relu(inp[map[j]]) ----------------
__global__ void gather_relu(const int* __restrict__ map) {
    int idx = blockIdx.x * 256 + threadIdx.x;
    if (idx >= NB * 75) return;
    int r = idx / 75, c = idx % 75;
    int4 m = ((const int4*)map)[r];
    const float4* S = (const float4*)g_inp;
    float4 a = S[(size_t)m.x * 75 + c];
    float4 b = S[(size_t)m.y * 75 + c];
    float4 cc = S[(size_t)m.z * 75 + c];
    float4 d = S[(size_t)m.w * 75 + c];
    float4 o;
    o.x = fmaxf(a.x, 0.f) + fmaxf(b.x, 0.f) + fmaxf(cc.x, 0.f) + fmaxf(d.x, 0.f);
    o.y = fmaxf(a.y, 0.f) + fmaxf(b.y, 0.f) + fmaxf(cc.y, 0.f) + fmaxf(d.y, 0.f);
    o.z = fmaxf(a.z, 0.f) + fmaxf(b.z, 0.f) + fmaxf(cc.z, 0.f) + fmaxf(d.z, 0.f);
    o.w = fmaxf(a.w, 0.f) + fmaxf(b.w, 0.f) + fmaxf(cc.w, 0.f) + fmaxf(d.w, 0.f);
    ((float4*)g_m1)[(size_t)r * 75 + c] = o;
}

// pack 4 floats -> 4 halves (uint2)
__device__ __forceinline__ uint2 pack4h(float a, float b, float c, float d) {
    union { uint2 u; __half h[4]; } r;
    r.h[0] = __float2half_rn(a); r.h[1] = __float2half_rn(b);
    r.h[2] = __float2half_rn(c); r.h[3] = __float2half_rn(d);
    return r.u;
}

// ---------------- gather2: m2 = fp16(sum_j m1[map[j]]) -> half [NB x 320] ----------------
__global__ void gather2(const int* __restrict__ map) {
    int idx = blockIdx.x * 256 + threadIdx.x;
    if (idx >= NB * 75) return;
    int r = idx / 75, c = idx % 75;
    int4 m = ((const int4*)map)[r];
    const float4* S = (const float4*)g_m1;
    float4 a = S[(size_t)m.x * 75 + c];
    float4 b = S[(size_t)m.y * 75 + c];
    float4 cc = S[(size_t)m.z * 75 + c];
    float4 d = S[(size_t)m.w * 75 + c];
    uint2 o = pack4h(a.x + b.x + cc.x + d.x, a.y + b.y + cc.y + d.y,
                     a.z + b.z + cc.z + d.z, a.w + b.w + cc.w + d.w);
    *(uint2*)&g_m2h[(size_t)r * KP2 + c * 4] = o;
}

// ---------------- gather_atom: msgs = fp16(sum_j h2[a2ib[j]]) -> half [NA x 300] ----------------
__global__ void gather_atom(const int* __restrict__ a2ib) {
    int idx = blockIdx.x * 256 + threadIdx.x;
    if (idx >= NA * 75) return;
    int r = idx / 75, c = idx % 75;
    int4 m = ((const int4*)a2ib)[r];
    const float4* S = (const float4*)g_h2;
    float4 a = S[(size_t)m.x * 75 + c];
    float4 b = S[(size_t)m.y * 75 + c];
    float4 cc = S[(size_t)m.z * 75 + c];
    float4 d = S[(size_t)m.w * 75 + c];
    uint2 o = pack4h(a.x + b.x + cc.x + d.x, a.y + b.y + cc.y + d.y,
                     a.z + b.z + cc.z + d.z, a.w + b.w + cc.w + d.w);
    *(uint2*)&g_msgsh[(size_t)r * DH + c * 4] = o;
}

// ---------------- FP16 GEMM: BM=128, BN=320, BK=32, 512 thr, 3 stages ----------------
// Warp grid 2(m) x 8(n); warp tile 64x40. smem rows: 32 halves + 8 pad = 80 B.
#define BOFF  10240                 // A: 128*80
#define STG   (BOFF + 320 * 80)     // + B: 25600 -> 35840
#define SMTOT (3 * STG)             // 107520

template <int MODE, int KP>
__global__ void __launch_bounds__(512)
mm_f16(const float* __restrict__ srcA,
       const float* __restrict__ bias, float* __restrict__ dOut) {
    constexpr int NCH = KP / 32;
    const __half* __restrict__ Wt = (MODE == 1) ? g_W1 : (MODE == 2) ? g_W2 : g_W3;

    extern __shared__ __align__(16) char smem[];
    const uint32_t sb = s2u(smem);
    const int tid = threadIdx.x, w = tid >> 5, lane = tid & 31;
    const int wr = w & 1, wc = w >> 1;       // warp tile 64x40
    const int rowBase = blockIdx.x * 128;

    float acc[4][5][4];
#pragma unroll
    for (int i = 0; i < 4; i++)
#pragma unroll
        for (int j = 0; j < 5; j++)
#pragma unroll
            for (int q = 0; q < 4; q++) acc[i][j][q] = 0.f;

    // ---- A producer (MODE 1/3): warp owns 8 rows, lane owns one k column ----
    __half rbuf[8];
    auto loadA_regs = [&](int c) {
        const int k = c * 32 + lane;
#pragma unroll
        for (int i = 0; i < 8; i++) {
            const int grow = rowBase + w * 8 + i;
            __half v = __float2half_rn(0.f);
            if (MODE == 1) {
                if (k < K1) v = __float2half_rn(srcA[(size_t)grow * K1 + k]);
            } else if (MODE == 3) {
                if (k < AF) v = __float2half_rn(srcA[(size_t)grow * AF + k]);
                else if (k >= 136 && k < 436) v = g_msgsh[(size_t)grow * DH + (k - 136)];
            }
            rbuf[i] = v;
        }
    };
    auto stsA = [&](int st) {
        char* p = smem + st * STG + (w * 8) * 80 + lane * 2;
#pragma unroll
        for (int i = 0; i < 8; i++) *(__half*)(p + i * 80) = rbuf[i];
    };

    // ---- A via cp.async (MODE 2): 128 rows x 4 segs = 512 = 1/thread ----
    auto cpA = [&](int c, int st) {
        const int row = tid >> 2, seg = tid & 3;
        cpa16(sb + st * STG + row * 80 + seg * 16,
              g_m2h + (size_t)(rowBase + row) * KP2 + c * 32 + seg * 8);
    };
    // ---- B: 320 rows x 4 segs = 1280 ----
    auto loadB = [&](int c, int st) {
#pragma unroll
        for (int i = tid; i < 1280; i += 512) {
            const int row = i >> 2, seg = i & 3;
            cpa16(sb + st * STG + BOFF + row * 80 + seg * 16,
                  Wt + (size_t)row * KP + c * 32 + seg * 8);
        }
    };

    // ---- prologue ----
    if (MODE != 2) {
        loadA_regs(0); stsA(0); loadB(0, 0); CP_COMMIT();
        loadA_regs(1); stsA(1); loadB(1, 1); CP_COMMIT();
        loadA_regs(2);
    } else {
        cpA(0, 0); loadB(0, 0); CP_COMMIT();
        cpA(1, 1); loadB(1, 1); CP_COMMIT();
    }

    // ldmatrix bases (proven R3 pattern, 80B rows)
    const uint32_t aOff = (uint32_t)(wr * 64 + (lane & 15)) * 80
                        + (uint32_t)(lane >> 4) * 16;
    const int bl = lane & 15;
    const uint32_t bOff = BOFF + (uint32_t)(wc * 40 + (bl & 7)) * 80
                        + (uint32_t)(bl >> 3) * 16;

    for (int c = 0; c < NCH; c++) {
        CP_WAIT1();
        __syncthreads();
        if (c + 2 < NCH) {
            const int st = (c + 2) % 3;
            if (MODE != 2) { stsA(st); }
            else          { cpA(c + 2, st); }
            loadB(c + 2, st);
        }
        CP_COMMIT();
        if (MODE != 2 && c + 3 < NCH) loadA_regs(c + 3);

        const uint32_t stp = sb + (c % 3) * STG;
#pragma unroll
        for (int kh = 0; kh < 2; kh++) {       // two k16 halves of the 32-chunk
            uint32_t af[4][4], bf[5][2];
#pragma unroll
            for (int mt = 0; mt < 4; mt++)
                ldmx4(af[mt], stp + aOff + mt * (16 * 80) + kh * 32);
#pragma unroll
            for (int nt = 0; nt < 5; nt++)
                ldmx2(bf[nt], stp + bOff + nt * (8 * 80) + kh * 32);
#pragma unroll
            for (int mt = 0; mt < 4; mt++)
#pragma unroll
                for (int nt = 0; nt < 5; nt++)
                    mma_f16(acc[mt][nt], af[mt], bf[nt]);
        }
    }

    if (MODE == 3) {
        // fused per-molecule mean readout: 128 rows = 4 molecules
        const int molBase = blockIdx.x * 4 + wr * 2;
#pragma unroll
        for (int mtb = 0; mtb < 4; mtb += 2) {
#pragma unroll
            for (int nt = 0; nt < 5; nt++) {
                const int col2 = wc * 40 + nt * 8 + (lane & 3) * 2;
                float b0 = 0.f, b1 = 0.f;
                if (col2 < DH) { b0 = bias[col2]; b1 = bias[col2 + 1]; }
                float s0 = 0.f, s1 = 0.f;
#pragma unroll
                for (int p = 0; p < 2; p++) {
#pragma unroll
                    for (int h = 0; h < 2; h++) {
                        s0 += fmaxf(acc[mtb + p][nt][h * 2]     + b0, 0.f);
                        s1 += fmaxf(acc[mtb + p][nt][h * 2 + 1] + b1, 0.f);
                    }
                }
#pragma unroll
                for (int off = 16; off >= 4; off >>= 1) {
                    s0 += __shfl_down_sync(0xFFFFFFFFu, s0, off);
                    s1 += __shfl_down_sync(0xFFFFFFFFu, s1, off);
                }
                if (lane < 4) {
                    const int colw = wc * 40 + nt * 8 + lane * 2;
                    if (colw < DH) {
                        const int mol = molBase + (mtb >> 1);
                        float2 v;
                        v.x = s0 * 0.03125f;
                        v.y = s1 * 0.03125f;
                        *(float2*)&dOut[(size_t)mol * OUTC + colw] = v;
                    }
                }
            }
        }
    } else {
        float* __restrict__ OUTp = (MODE == 1) ? g_inp : g_h2;
        const int crow = lane >> 2, cc0 = (lane & 3) * 2;
#pragma unroll
        for (int mt = 0; mt < 4; mt++) {
#pragma unroll
            for (int nt = 0; nt < 5; nt++) {
                const int col = wc * 40 + nt * 8 + cc0;
                if (col >= DH) continue;
#pragma unroll
                for (int half = 0; half < 2; half++) {
                    const int grow = rowBase + wr * 64 + mt * 16 + crow + half * 8;
                    const size_t o = (size_t)grow * DH + col;
                    float v0 = acc[mt][nt][half * 2];
                    float v1 = acc[mt][nt][half * 2 + 1];
                    if (MODE == 2) {
                        float2 pv = *(const float2*)&g_inp[o];
                        v0 = fmaxf(pv.x + v0, 0.f);
                        v1 = fmaxf(pv.y + v1, 0.f);
                    }
                    float2 r; r.x = v0; r.y = v1;
                    *(float2*)&OUTp[o] = r;
                }
            }
        }
    }
}

// ---------------- global-feature concat ----------------
__global__ void glob_copy(const float* __restrict__ g, float* __restrict__ out) {
    int idx = blockIdx.x * 256 + threadIdx.x;
    if (idx >= NM * 32) return;
    int mol = idx >> 5, j4 = idx & 31;
    float4 v = ((const float4*)g)[mol * 32 + j4];
    *(float4*)&out[(size_t)mol * OUTC + 300 + 4 * j4] = v;
}

// ---------------- launch ----------------
extern "C" void kernel_launch(void* const* d_in, const int* in_sizes, int n_in,
                              void* d_out, int out_size) {
    const float* atom_features   = (const float*)d_in[0];
    const float* f_ini           = (const float*)d_in[1];
    const float* global_features = (const float*)d_in[2];
    const float* W_i             = (const float*)d_in[3];
    const float* W_h             = (const float*)d_in[4];
    const float* W_o             = (const float*)d_in[5];
    const float* b_o             = (const float*)d_in[6];
    const int*   a2ib            = (const int*)d_in[7];
    const int*   mapping         = (const int*)d_in[8];
    float* out = (float*)d_out;

    static bool cfg = false;
    if (!cfg) {
        cudaFuncSetAttribute(mm_f16<1, KP1>, cudaFuncAttributeMaxDynamicSharedMemorySize, SMTOT);
        cudaFuncSetAttribute(mm_f16<2, KP2>, cudaFuncAttributeMaxDynamicSharedMemorySize, SMTOT);
        cudaFuncSetAttribute(mm_f16<3, KP3>, cudaFuncAttributeMaxDynamicSharedMemorySize, SMTOT);
        cfg = true;
    }

    glob_copy<<<(NM * 32 + 255) / 256, 256>>>(global_features, out);
    prep_all<<<(320 * (KP1 + KP2 + KP3) + 255) / 256, 256>>>(W_i, W_h, W_o);

    // 1) inp = f_ini @ W_i               [pad fused into A producer]
    mm_f16<1, KP1><<<NB / 128, 512, SMTOT>>>(f_ini, nullptr, nullptr);
    // 2) m1 = sum relu(inp[mapping])
    gather_relu<<<(NB * 75 + 255) / 256, 256>>>(mapping);
    // 3) m2 = fp16(sum m1[mapping])
    gather2<<<(NB * 75 + 255) / 256, 256>>>(mapping);
    // 4) h2 = relu(inp + m2 @ W_h)
    mm_f16<2, KP2><<<NB / 128, 512, SMTOT>>>(nullptr, nullptr, nullptr);
    // 5) msgs = fp16(sum h2[a2ib])
    gather_atom<<<(NA * 75 + 255) / 256, 256>>>(a2ib);
    // 6+7) out = mean(relu([atomF | msgs] @ W_o + b_o))   [readout fused]
    mm_f16<3, KP3><<<NA / 128, 512, SMTOT>>>(atom_features, b_o, out);
}

// round 10
// speedup vs baseline: 2.7059x; 1.2134x over previous
#include <cuda_runtime.h>
#include <cuda_fp16.h>
#include <cstdint>

#define NB 131072
#define NA 65536
#define NM 2048
#define DH 300
#define AF 133
#define K1 147
#define GF 128
#define OUTC 428

#define KP1 160
#define KP2 320
#define KP3 448

// ---------------- device scratch ----------------
__device__ __align__(16) __half g_W1[320 * KP1];
__device__ __align__(16) __half g_W2[320 * KP2];
__device__ __align__(16) __half g_W3[320 * KP3];
__device__ __align__(16) __half g_inph [(size_t)NB * DH];
__device__ __align__(16) __half g_m1h  [(size_t)NB * DH];
__device__ __align__(16) __half g_m2h  [(size_t)NB * KP2];   // cols 300..319 stay 0
__device__ __align__(16) __half g_h2h  [(size_t)NB * DH];
__device__ __align__(16) __half g_msgsh[(size_t)NA * DH];

// ---------------- helpers ----------------
__device__ __forceinline__ uint32_t s2u(const void* p) {
    uint32_t a;
    asm("{ .reg .u64 t; cvta.to.shared.u64 t, %1; cvt.u32.u64 %0, t; }"
        : "=r"(a) : "l"(p));
    return a;
}
__device__ __forceinline__ void cpa16(uint32_t s, const void* g) {
    asm volatile("cp.async.cg.shared.global [%0], [%1], 16;" :: "r"(s), "l"(g));
}
#define CP_COMMIT() asm volatile("cp.async.commit_group;" ::: "memory")
#define CP_WAIT1()  asm volatile("cp.async.wait_group 1;" ::: "memory")

__device__ __forceinline__ void ldmx4(uint32_t* r, uint32_t a) {
    asm volatile("ldmatrix.sync.aligned.m8n8.x4.shared.b16 {%0,%1,%2,%3}, [%4];"
                 : "=r"(r[0]), "=r"(r[1]), "=r"(r[2]), "=r"(r[3]) : "r"(a));
}
__device__ __forceinline__ void ldmx2(uint32_t* r, uint32_t a) {
    asm volatile("ldmatrix.sync.aligned.m8n8.x2.shared.b16 {%0,%1}, [%2];"
                 : "=r"(r[0]), "=r"(r[1]) : "r"(a));
}
__device__ __forceinline__ void mma_f16(float* c, const uint32_t* a, const uint32_t* b) {
    asm volatile(
        "mma.sync.aligned.m16n8k16.row.col.f32.f16.f16.f32 "
        "{%0,%1,%2,%3}, {%4,%5,%6,%7}, {%8,%9}, {%0,%1,%2,%3};"
        : "+f"(c[0]), "+f"(c[1]), "+f"(c[2]), "+f"(c[3])
        : "r"(a[0]), "r"(a[1]), "r"(a[2]), "r"(a[3]), "r"(b[0]), "r"(b[1]));
}
// unpack uint (2 halves) to two floats
__device__ __forceinline__ float2 h2f(uint32_t u) {
    return __half22float2(*(__half2*)&u);
}
__device__ __forceinline__ uint2 pack4h(float a, float b, float c, float d) {
    union { uint2 u; __half h[4]; } r;
    r.h[0] = __float2half_rn(a); r.h[1] = __float2half_rn(b);
    r.h[2] = __float2half_rn(c); r.h[3] = __float2half_rn(d);
    return r.u;
}

// ---------------- weight prep (one launch for all 3) ----------------
__global__ void prep_all(const float* __restrict__ W1s,
                         const float* __restrict__ W2s,
                         const float* __restrict__ W3s) {
    int idx = blockIdx.x * 256 + threadIdx.x;
    const int T1 = 320 * KP1, T2 = 320 * KP2;
    const float* W;
    __half* B;
    int KP, mode;
    if (idx < T1) { W = W1s; B = g_W1; KP = KP1; mode = 1; }
    else if (idx < T1 + T2) { idx -= T1; W = W2s; B = g_W2; KP = KP2; mode = 2; }
    else {
        idx -= T1 + T2;
        if (idx >= 320 * KP3) return;
        W = W3s; B = g_W3; KP = KP3; mode = 3;
    }
    int n = idx / KP, k = idx % KP;
    int src;
    if (mode == 3) src = (k < 133) ? k : (k >= 136 && k < 436) ? k - 3 : -1;
    else if (mode == 1) src = (k < K1) ? k : -1;
    else src = (k < DH) ? k : -1;
    float v = (n < 300 && src >= 0) ? W[src * 300 + n] : 0.f;
    B[(size_t)n * KP + k] = __float2half_rn(v);
}

// ---------------- gather1: m1h = fp16(sum_j relu(inph[map[j]])) ----------------
__global__ void gather_relu(const int* __restrict__ map) {
    int idx = blockIdx.x * 256 + threadIdx.x;
    if (idx >= NB * 75) return;
    int r = idx / 75, c = idx % 75;
    int4 m = ((const int4*)map)[r];
    const uint2* S = (const uint2*)g_inph;
    uint2 a = S[(size_t)m.x * 75 + c];
    uint2 b = S[(size_t)m.y * 75 + c];
    uint2 cc = S[(size_t)m.z * 75 + c];
    uint2 d = S[(size_t)m.w * 75 + c];
    float2 a0 = h2f(a.x), a1 = h2f(a.y);
    float2 b0 = h2f(b.x), b1 = h2f(b.y);
    float2 c0 = h2f(cc.x), c1 = h2f(cc.y);
    float2 d0 = h2f(d.x), d1 = h2f(d.y);
    uint2 o = pack4h(
        fmaxf(a0.x, 0.f) + fmaxf(b0.x, 0.f) + fmaxf(c0.x, 0.f) + fmaxf(d0.x, 0.f),
        fmaxf(a0.y, 0.f) + fmaxf(b0.y, 0.f) + fmaxf(c0.y, 0.f) + fmaxf(d0.y, 0.f),
        fmaxf(a1.x, 0.f) + fmaxf(b1.x, 0.f) + fmaxf(c1.x, 0.f) + fmaxf(d1.x, 0.f),
        fmaxf(a1.y, 0.f) + fmaxf(b1.y, 0.f) + fmaxf(c1.y, 0.f) + fmaxf(d1.y, 0.f));
    ((uint2*)g_m1h)[(size_t)r * 75 + c] = o;
}

// ---------------- gather2: m2h = fp16(sum_j m1h[map[j]]) -> [NB x 320] ----------------
__global__ void gather2(const int* __restrict__ map) {
    int idx = blockIdx.x * 256 + threadIdx.x;
    if (idx >= NB * 75) return;
    int r = idx / 75, c = idx % 75;
    int4 m = ((const int4*)map)[r];
    const uint2* S = (const uint2*)g_m1h;
    uint2 a = S[(size_t)m.x * 75 + c];
    uint2 b = S[(size_t)m.y * 75 + c];
    uint2 cc = S[(size_t)m.z * 75 + c];
    uint2 d = S[(size_t)m.w * 75 + c];
    float2 a0 = h2f(a.x), a1 = h2f(a.y);
    float2 b0 = h2f(b.x), b1 = h2f(b.y);
    float2 c0 = h2f(cc.x), c1 = h2f(cc.y);
    float2 d0 = h2f(d.x), d1 = h2f(d.y);
    uint2 o = pack4h(a0.x + b0.x + c0.x + d0.x, a0.y + b0.y + c0.y + d0.y,
                     a1.x + b1.x + c1.x + d1.x, a1.y + b1.y + c1.y + d1.y);
    *(uint2*)&g_m2h[(size_t)r * KP2 + c * 4] = o;
}

// ---------------- gather_atom: msgs = fp16(sum_j h2h[a2ib[j]]) ----------------
__global__ void gather_atom(const int* __restrict__ a2ib) {
    int idx = blockIdx.x * 256 + threadIdx.x;
    if (idx >= NA * 75) return;
    int r = idx / 75, c = idx % 75;
    int4 m = ((const int4*)a2ib)[r];
    const uint2* S = (const uint2*)g_h2h;
    uint2 a = S[(size_t)m.x * 75 + c];
    uint2 b = S[(size_t)m.y * 75 + c];
    uint2 cc = S[(size_t)m.z * 75 + c];
    uint2 d = S[(size_t)m.w * 75 + c];
    float2 a0 = h2f(a.x), a1 = h2f(a.y);
    float2 b0 = h2f(b.x), b1 = h2f(b.y);
    float2 c0 = h2f(cc.x), c1 = h2f(cc.y);
    float2 d0 = h2f(d.x), d1 = h2f(d.y);
    uint2 o = pack4h(a0.x + b0.x + c0.x + d0.x, a0.y + b0.y + c0.y + d0.y,
                     a1.x + b1.x + c1.x + d1.x, a1.y + b1.y + c1.y + d1.y);
    ((uint2*)g_msgsh)[(size_t)r * 75 + c] = o;
}

// ---------------- FP16 GEMM: BM=128, BN=320, BK=32, 512 thr, 3 stages ----------------
#define BOFF  10240                 // A: 128*80
#define STG   (BOFF + 320 * 80)     // + B: 25600 -> 35840
#define SMTOT (3 * STG)             // 107520

template <int MODE, int KP>
__global__ void __launch_bounds__(512)
mm_f16(const float* __restrict__ srcA,
       const float* __restrict__ bias, float* __restrict__ dOut) {
    constexpr int NCH = KP / 32;
    const __half* __restrict__ Wt = (MODE == 1) ? g_W1 : (MODE == 2) ? g_W2 : g_W3;

    extern __shared__ __align__(16) char smem[];
    const uint32_t sb = s2u(smem);
    const int tid = threadIdx.x, w = tid >> 5, lane = tid & 31;
    const int wr = w & 1, wc = w >> 1;       // warp tile 64x40
    const int rowBase = blockIdx.x * 128;

    float acc[4][5][4];
#pragma unroll
    for (int i = 0; i < 4; i++)
#pragma unroll
        for (int j = 0; j < 5; j++)
#pragma unroll
            for (int q = 0; q < 4; q++) acc[i][j][q] = 0.f;

    // ---- A producer (MODE 1/3): warp owns 8 rows, lane owns one k column ----
    __half rbuf[8];
    auto loadA_regs = [&](int c) {
        const int k = c * 32 + lane;
#pragma unroll
        for (int i = 0; i < 8; i++) {
            const int grow = rowBase + w * 8 + i;
            __half v = __float2half_rn(0.f);
            if (MODE == 1) {
                if (k < K1) v = __float2half_rn(srcA[(size_t)grow * K1 + k]);
            } else if (MODE == 3) {
                if (k < AF) v = __float2half_rn(srcA[(size_t)grow * AF + k]);
                else if (k >= 136 && k < 436) v = g_msgsh[(size_t)grow * DH + (k - 136)];
            }
            rbuf[i] = v;
        }
    };
    auto stsA = [&](int st) {
        char* p = smem + st * STG + (w * 8) * 80 + lane * 2;
#pragma unroll
        for (int i = 0; i < 8; i++) *(__half*)(p + i * 80) = rbuf[i];
    };

    // ---- A via cp.async (MODE 2): 128 rows x 4 segs = 512 = 1/thread ----
    auto cpA = [&](int c, int st) {
        const int row = tid >> 2, seg = tid & 3;
        cpa16(sb + st * STG + row * 80 + seg * 16,
              g_m2h + (size_t)(rowBase + row) * KP2 + c * 32 + seg * 8);
    };
    // ---- B: 320 rows x 4 segs = 1280 ----
    auto loadB = [&](int c, int st) {
#pragma unroll
        for (int i = tid; i < 1280; i += 512) {
            const int row = i >> 2, seg = i & 3;
            cpa16(sb + st * STG + BOFF + row * 80 + seg * 16,
                  Wt + (size_t)row * KP + c * 32 + seg * 8);
        }
    };

    // ---- prologue ----
    if (MODE != 2) {
        loadA_regs(0); stsA(0); loadB(0, 0); CP_COMMIT();
        loadA_regs(1); stsA(1); loadB(1, 1); CP_COMMIT();
        loadA_regs(2);
    } else {
        cpA(0, 0); loadB(0, 0); CP_COMMIT();
        cpA(1, 1); loadB(1, 1); CP_COMMIT();
    }

    // ldmatrix bases (80 B rows)
    const uint32_t aOff = (uint32_t)(wr * 64 + (lane & 15)) * 80
                        + (uint32_t)(lane >> 4) * 16;
    const int bl = lane & 15;
    const uint32_t bOff = BOFF + (uint32_t)(wc * 40 + (bl & 7)) * 80
                        + (uint32_t)(bl >> 3) * 16;

    for (int c = 0; c < NCH; c++) {
        CP_WAIT1();
        __syncthreads();
        if (c + 2 < NCH) {
            const int st = (c + 2) % 3;
            if (MODE != 2) { stsA(st); }
            else          { cpA(c + 2, st); }
            loadB(c + 2, st);
        }
        CP_COMMIT();
        if (MODE != 2 && c + 3 < NCH) loadA_regs(c + 3);

        const uint32_t stp = sb + (c % 3) * STG;
#pragma unroll
        for (int kh = 0; kh < 2; kh++) {
            uint32_t af[4][4], bf[5][2];
#pragma unroll
            for (int mt = 0; mt < 4; mt++)
                ldmx4(af[mt], stp + aOff + mt * (16 * 80) + kh * 32);
#pragma unroll
            for (int nt = 0; nt < 5; nt++)
                ldmx2(bf[nt], stp + bOff + nt * (8 * 80) + kh * 32);
#pragma unroll
            for (int mt = 0; mt < 4; mt++)
#pragma unroll
                for (int nt = 0; nt < 5; nt++)
                    mma_f16(acc[mt][nt], af[mt], bf[nt]);
        }
    }

    if (MODE == 3) {
        // fused per-molecule mean readout: 128 rows = 4 molecules
        const int molBase = blockIdx.x * 4 + wr * 2;
#pragma unroll
        for (int mtb = 0; mtb < 4; mtb += 2) {
#pragma unroll
            for (int nt = 0; nt < 5; nt++) {
                const int col2 = wc * 40 + nt * 8 + (lane & 3) * 2;
                float b0 = 0.f, b1 = 0.f;
                if (col2 < DH) { b0 = bias[col2]; b1 = bias[col2 + 1]; }
                float s0 = 0.f, s1 = 0.f;
#pragma unroll
                for (int p = 0; p < 2; p++) {
#pragma unroll
                    for (int h = 0; h < 2; h++) {
                        s0 += fmaxf(acc[mtb + p][nt][h * 2]     + b0, 0.f);
                        s1 += fmaxf(acc[mtb + p][nt][h * 2 + 1] + b1, 0.f);
                    }
                }
#pragma unroll
                for (int off = 16; off >= 4; off >>= 1) {
                    s0 += __shfl_down_sync(0xFFFFFFFFu, s0, off);
                    s1 += __shfl_down_sync(0xFFFFFFFFu, s1, off);
                }
                if (lane < 4) {
                    const int colw = wc * 40 + nt * 8 + lane * 2;
                    if (colw < DH) {
                        const int mol = molBase + (mtb >> 1);
                        float2 v;
                        v.x = s0 * 0.03125f;
                        v.y = s1 * 0.03125f;
                        *(float2*)&dOut[(size_t)mol * OUTC + colw] = v;
                    }
                }
            }
        }
    } else {
        __half* __restrict__ OUTp = (MODE == 1) ? g_inph : g_h2h;
        const int crow = lane >> 2, cc0 = (lane & 3) * 2;
#pragma unroll
        for (int mt = 0; mt < 4; mt++) {
#pragma unroll
            for (int nt = 0; nt < 5; nt++) {
                const int col = wc * 40 + nt * 8 + cc0;
                if (col >= DH) continue;
#pragma unroll
                for (int half = 0; half < 2; half++) {
                    const int grow = rowBase + wr * 64 + mt * 16 + crow + half * 8;
                    const size_t o = (size_t)grow * DH + col;
                    float v0 = acc[mt][nt][half * 2];
                    float v1 = acc[mt][nt][half * 2 + 1];
                    if (MODE == 2) {
                        float2 pv = __half22float2(*(const __half2*)&g_inph[o]);
                        v0 = fmaxf(pv.x + v0, 0.f);
                        v1 = fmaxf(pv.y + v1, 0.f);
                    }
                    *(__half2*)&OUTp[o] = __floats2half2_rn(v0, v1);
                }
            }
        }
    }
}

// ---------------- global-feature concat ----------------
__global__ void glob_copy(const float* __restrict__ g, float* __restrict__ out) {
    int idx = blockIdx.x * 256 + threadIdx.x;
    if (idx >= NM * 32) return;
    int mol = idx >> 5, j4 = idx & 31;
    float4 v = ((const float4*)g)[mol * 32 + j4];
    *(float4*)&out[(size_t)mol * OUTC + 300 + 4 * j4] = v;
}

// ---------------- launch ----------------
extern "C" void kernel_launch(void* const* d_in, const int* in_sizes, int n_in,
                              void* d_out, int out_size) {
    const float* atom_features   = (const float*)d_in[0];
    const float* f_ini           = (const float*)d_in[1];
    const float* global_features = (const float*)d_in[2];
    const float* W_i             = (const float*)d_in[3];
    const float* W_h             = (const float*)d_in[4];
    const float* W_o             = (const float*)d_in[5];
    const float* b_o             = (const float*)d_in[6];
    const int*   a2ib            = (const int*)d_in[7];
    const int*   mapping         = (const int*)d_in[8];
    float* out = (float*)d_out;

    static bool cfg = false;
    if (!cfg) {
        cudaFuncSetAttribute(mm_f16<1, KP1>, cudaFuncAttributeMaxDynamicSharedMemorySize, SMTOT);
        cudaFuncSetAttribute(mm_f16<2, KP2>, cudaFuncAttributeMaxDynamicSharedMemorySize, SMTOT);
        cudaFuncSetAttribute(mm_f16<3, KP3>, cudaFuncAttributeMaxDynamicSharedMemorySize, SMTOT);
        cfg = true;
    }

    glob_copy<<<(NM * 32 + 255) / 256, 256>>>(global_features, out);
    prep_all<<<(320 * (KP1 + KP2 + KP3) + 255) / 256, 256>>>(W_i, W_h, W_o);

    // 1) inp = f_ini @ W_i  (stored fp16)
    mm_f16<1, KP1><<<NB / 128, 512, SMTOT>>>(f_ini, nullptr, nullptr);
    // 2) m1 = fp16(sum relu(inp[mapping]))
    gather_relu<<<(NB * 75 + 255) / 256, 256>>>(mapping);
    // 3) m2 = fp16(sum m1[mapping])
    gather2<<<(NB * 75 + 255) / 256, 256>>>(mapping);
    // 4) h2 = fp16(relu(inp + m2 @ W_h))
    mm_f16<2, KP2><<<NB / 128, 512, SMTOT>>>(nullptr, nullptr, nullptr);
    // 5) msgs = fp16(sum h2[a2ib])
    gather_atom<<<(NA * 75 + 255) / 256, 256>>>(a2ib);
    // 6+7) out = mean(relu([atomF | msgs] @ W_o + b_o))   [readout fused]
    mm_f16<3, KP3><<<NA / 128, 512, SMTOT>>>(atom_features, b_o, out);
}

// round 11
// speedup vs baseline: 2.9444x; 1.0881x over previous
#include <cuda_runtime.h>
#include <cuda_fp16.h>
#include <cstdint>

#define NB 131072
#define NA 65536
#define NM 2048
#define DH 300
#define AF 133
#define K1 147
#define GF 128
#define OUTC 428

#define KP1 160
#define KP2 320
#define KP3 448

#define SROW 304            // padded intermediate row stride (halves)
#define SR4  38             // = SROW/8, uint4 per row

// ---------------- device scratch ----------------
__device__ __align__(16) __half g_W1[320 * KP1];
__device__ __align__(16) __half g_W2[320 * KP2];
__device__ __align__(16) __half g_W3[320 * KP3];
__device__ __align__(16) __half g_inph [(size_t)NB * SROW];
__device__ __align__(16) __half g_m1h  [(size_t)NB * SROW];
__device__ __align__(16) __half g_m2h  [(size_t)NB * KP2];   // cols 304..319 stay 0
__device__ __align__(16) __half g_h2h  [(size_t)NB * SROW];
__device__ __align__(16) __half g_msgsh[(size_t)NA * SROW];

// ---------------- helpers ----------------
__device__ __forceinline__ uint32_t s2u(const void* p) {
    uint32_t a;
    asm("{ .reg .u64 t; cvta.to.shared.u64 t, %1; cvt.u32.u64 %0, t; }"
        : "=r"(a) : "l"(p));
    return a;
}
__device__ __forceinline__ void cpa16(uint32_t s, const void* g) {
    asm volatile("cp.async.cg.shared.global [%0], [%1], 16;" :: "r"(s), "l"(g));
}
#define CP_COMMIT() asm volatile("cp.async.commit_group;" ::: "memory")
#define CP_WAIT1()  asm volatile("cp.async.wait_group 1;" ::: "memory")

__device__ __forceinline__ void ldmx4(uint32_t* r, uint32_t a) {
    asm volatile("ldmatrix.sync.aligned.m8n8.x4.shared.b16 {%0,%1,%2,%3}, [%4];"
                 : "=r"(r[0]), "=r"(r[1]), "=r"(r[2]), "=r"(r[3]) : "r"(a));
}
__device__ __forceinline__ void ldmx2(uint32_t* r, uint32_t a) {
    asm volatile("ldmatrix.sync.aligned.m8n8.x2.shared.b16 {%0,%1}, [%2];"
                 : "=r"(r[0]), "=r"(r[1]) : "r"(a));
}
__device__ __forceinline__ void mma_f16(float* c, const uint32_t* a, const uint32_t* b) {
    asm volatile(
        "mma.sync.aligned.m16n8k16.row.col.f32.f16.f16.f32 "
        "{%0,%1,%2,%3}, {%4,%5,%6,%7}, {%8,%9}, {%0,%1,%2,%3};"
        : "+f"(c[0]), "+f"(c[1]), "+f"(c[2]), "+f"(c[3])
        : "r"(a[0]), "r"(a[1]), "r"(a[2]), "r"(a[3]), "r"(b[0]), "r"(b[1]));
}
__device__ __forceinline__ __half2 u2h(uint32_t u) { return *(__half2*)&u; }
__device__ __forceinline__ uint32_t h2u(__half2 h) { return *(uint32_t*)&h; }

// relu+sum of 4 half2 (relu exact; adds round @2^-11)
__device__ __forceinline__ uint32_t rsum4(uint32_t a, uint32_t b, uint32_t c, uint32_t d) {
    const __half2 z = __float2half2_rn(0.f);
    __half2 r = __hadd2(__hadd2(__hmax2(u2h(a), z), __hmax2(u2h(b), z)),
                        __hadd2(__hmax2(u2h(c), z), __hmax2(u2h(d), z)));
    return h2u(r);
}
__device__ __forceinline__ uint32_t sum4(uint32_t a, uint32_t b, uint32_t c, uint32_t d) {
    __half2 r = __hadd2(__hadd2(u2h(a), u2h(b)), __hadd2(u2h(c), u2h(d)));
    return h2u(r);
}

// ---------------- weight prep (one launch for all 3) ----------------
__global__ void prep_all(const float* __restrict__ W1s,
                         const float* __restrict__ W2s,
                         const float* __restrict__ W3s) {
    int idx = blockIdx.x * 256 + threadIdx.x;
    const int T1 = 320 * KP1, T2 = 320 * KP2;
    const float* W;
    __half* B;
    int KP, mode;
    if (idx < T1) { W = W1s; B = g_W1; KP = KP1; mode = 1; }
    else if (idx < T1 + T2) { idx -= T1; W = W2s; B = g_W2; KP = KP2; mode = 2; }
    else {
        idx -= T1 + T2;
        if (idx >= 320 * KP3) return;
        W = W3s; B = g_W3; KP = KP3; mode = 3;
    }
    int n = idx / KP, k = idx % KP;
    int src;
    if (mode == 3) src = (k < 133) ? k : (k >= 136 && k < 436) ? k - 3 : -1;
    else if (mode == 1) src = (k < K1) ? k : -1;
    else src = (k < DH) ? k : -1;
    float v = (n < 300 && src >= 0) ? W[src * 300 + n] : 0.f;
    B[(size_t)n * KP + k] = __float2half_rn(v);
}

// ---------------- gather1: m1h = sum_j relu(inph[map[j]])  (half2 math, uint4 IO) ----
__global__ void gather_relu(const int* __restrict__ map) {
    int idx = blockIdx.x * 256 + threadIdx.x;
    if (idx >= NB * SR4) return;
    int r = idx / SR4, c = idx % SR4;
    int4 m = ((const int4*)map)[r];
    const uint4* S = (const uint4*)g_inph;
    uint4 a = S[(size_t)m.x * SR4 + c];
    uint4 b = S[(size_t)m.y * SR4 + c];
    uint4 cc = S[(size_t)m.z * SR4 + c];
    uint4 d = S[(size_t)m.w * SR4 + c];
    uint4 o;
    o.x = rsum4(a.x, b.x, cc.x, d.x);
    o.y = rsum4(a.y, b.y, cc.y, d.y);
    o.z = rsum4(a.z, b.z, cc.z, d.z);
    o.w = rsum4(a.w, b.w, cc.w, d.w);
    ((uint4*)g_m1h)[(size_t)r * SR4 + c] = o;
}

// ---------------- gather2: m2h = sum_j m1h[map[j]] -> [NB x 320] ----------------
__global__ void gather2(const int* __restrict__ map) {
    int idx = blockIdx.x * 256 + threadIdx.x;
    if (idx >= NB * SR4) return;
    int r = idx / SR4, c = idx % SR4;
    int4 m = ((const int4*)map)[r];
    const uint4* S = (const uint4*)g_m1h;
    uint4 a = S[(size_t)m.x * SR4 + c];
    uint4 b = S[(size_t)m.y * SR4 + c];
    uint4 cc = S[(size_t)m.z * SR4 + c];
    uint4 d = S[(size_t)m.w * SR4 + c];
    uint4 o;
    o.x = sum4(a.x, b.x, cc.x, d.x);
    o.y = sum4(a.y, b.y, cc.y, d.y);
    o.z = sum4(a.z, b.z, cc.z, d.z);
    o.w = sum4(a.w, b.w, cc.w, d.w);
    *(uint4*)&g_m2h[(size_t)r * KP2 + c * 8] = o;
}

// ---------------- gather_atom: msgs = sum_j h2h[a2ib[j]] ----------------
__global__ void gather_atom(const int* __restrict__ a2ib) {
    int idx = blockIdx.x * 256 + threadIdx.x;
    if (idx >= NA * SR4) return;
    int r = idx / SR4, c = idx % SR4;
    int4 m = ((const int4*)a2ib)[r];
    const uint4* S = (const uint4*)g_h2h;
    uint4 a = S[(size_t)m.x * SR4 + c];
    uint4 b = S[(size_t)m.y * SR4 + c];
    uint4 cc = S[(size_t)m.z * SR4 + c];
    uint4 d = S[(size_t)m.w * SR4 + c];
    uint4 o;
    o.x = sum4(a.x, b.x, cc.x, d.x);
    o.y = sum4(a.y, b.y, cc.y, d.y);
    o.z = sum4(a.z, b.z, cc.z, d.z);
    o.w = sum4(a.w, b.w, cc.w, d.w);
    ((uint4*)g_msgsh)[(size_t)r * SR4 + c] = o;
}

// ---------------- FP16 GEMM: BM=128, BN=320, BK=32, 512 thr, 3 stages ----------------
#define BOFF  10240                 // A: 128*80
#define STG   (BOFF + 320 * 80)     // + B: 25600 -> 35840
#define SMTOT (3 * STG)             // 107520

template <int MODE, int KP>
__global__ void __launch_bounds__(512)
mm_f16(const float* __restrict__ srcA,
       const float* __restrict__ bias, float* __restrict__ dOut) {
    constexpr int NCH = KP / 32;
    const __half* __restrict__ Wt = (MODE == 1) ? g_W1 : (MODE == 2) ? g_W2 : g_W3;

    extern __shared__ __align__(16) char smem[];
    const uint32_t sb = s2u(smem);
    const int tid = threadIdx.x, w = tid >> 5, lane = tid & 31;
    const int wr = w & 1, wc = w >> 1;       // warp tile 64x40
    const int rowBase = blockIdx.x * 128;

    float acc[4][5][4];
#pragma unroll
    for (int i = 0; i < 4; i++)
#pragma unroll
        for (int j = 0; j < 5; j++)
#pragma unroll
            for (int q = 0; q < 4; q++) acc[i][j][q] = 0.f;

    // ---- A producer (MODE 1/3): warp owns 8 rows, lane owns one k column ----
    __half rbuf[8];
    auto loadA_regs = [&](int c) {
        const int k = c * 32 + lane;
#pragma unroll
        for (int i = 0; i < 8; i++) {
            const int grow = rowBase + w * 8 + i;
            __half v = __float2half_rn(0.f);
            if (MODE == 1) {
                if (k < K1) v = __float2half_rn(srcA[(size_t)grow * K1 + k]);
            } else if (MODE == 3) {
                if (k < AF) v = __float2half_rn(srcA[(size_t)grow * AF + k]);
                else if (k >= 136 && k < 436) v = g_msgsh[(size_t)grow * SROW + (k - 136)];
            }
            rbuf[i] = v;
        }
    };
    auto stsA = [&](int st) {
        char* p = smem + st * STG + (w * 8) * 80 + lane * 2;
#pragma unroll
        for (int i = 0; i < 8; i++) *(__half*)(p + i * 80) = rbuf[i];
    };

    // ---- A via cp.async (MODE 2): 128 rows x 4 segs = 512 = 1/thread ----
    auto cpA = [&](int c, int st) {
        const int row = tid >> 2, seg = tid & 3;
        cpa16(sb + st * STG + row * 80 + seg * 16,
              g_m2h + (size_t)(rowBase + row) * KP2 + c * 32 + seg * 8);
    };
    // ---- B: 320 rows x 4 segs = 1280 ----
    auto loadB = [&](int c, int st) {
#pragma unroll
        for (int i = tid; i < 1280; i += 512) {
            const int row = i >> 2, seg = i & 3;
            cpa16(sb + st * STG + BOFF + row * 80 + seg * 16,
                  Wt + (size_t)row * KP + c * 32 + seg * 8);
        }
    };

    // ---- prologue ----
    if (MODE != 2) {
        loadA_regs(0); stsA(0); loadB(0, 0); CP_COMMIT();
        loadA_regs(1); stsA(1); loadB(1, 1); CP_COMMIT();
        loadA_regs(2);
    } else {
        cpA(0, 0); loadB(0, 0); CP_COMMIT();
        cpA(1, 1); loadB(1, 1); CP_COMMIT();
    }

    // ldmatrix bases (80 B rows)
    const uint32_t aOff = (uint32_t)(wr * 64 + (lane & 15)) * 80
                        + (uint32_t)(lane >> 4) * 16;
    const int bl = lane & 15;
    const uint32_t bOff = BOFF + (uint32_t)(wc * 40 + (bl & 7)) * 80
                        + (uint32_t)(bl >> 3) * 16;

    for (int c = 0; c < NCH; c++) {
        CP_WAIT1();
        __syncthreads();
        if (c + 2 < NCH) {
            const int st = (c + 2) % 3;
            if (MODE != 2) { stsA(st); }
            else          { cpA(c + 2, st); }
            loadB(c + 2, st);
        }
        CP_COMMIT();
        if (MODE != 2 && c + 3 < NCH) loadA_regs(c + 3);

        const uint32_t stp = sb + (c % 3) * STG;
#pragma unroll
        for (int kh = 0; kh < 2; kh++) {
            uint32_t af[4][4], bf[5][2];
#pragma unroll
            for (int mt = 0; mt < 4; mt++)
                ldmx4(af[mt], stp + aOff + mt * (16 * 80) + kh * 32);
#pragma unroll
            for (int nt = 0; nt < 5; nt++)
                ldmx2(bf[nt], stp + bOff + nt * (8 * 80) + kh * 32);
#pragma unroll
            for (int mt = 0; mt < 4; mt++)
#pragma unroll
                for (int nt = 0; nt < 5; nt++)
                    mma_f16(acc[mt][nt], af[mt], bf[nt]);
        }
    }

    if (MODE == 3) {
        // fused per-molecule mean readout: 128 rows = 4 molecules
        const int molBase = blockIdx.x * 4 + wr * 2;
#pragma unroll
        for (int mtb = 0; mtb < 4; mtb += 2) {
#pragma unroll
            for (int nt = 0; nt < 5; nt++) {
                const int col2 = wc * 40 + nt * 8 + (lane & 3) * 2;
                float b0 = 0.f, b1 = 0.f;
                if (col2 < DH) { b0 = bias[col2]; b1 = bias[col2 + 1]; }
                float s0 = 0.f, s1 = 0.f;
#pragma unroll
                for (int p = 0; p < 2; p++) {
#pragma unroll
                    for (int h = 0; h < 2; h++) {
                        s0 += fmaxf(acc[mtb + p][nt][h * 2]     + b0, 0.f);
                        s1 += fmaxf(acc[mtb + p][nt][h * 2 + 1] + b1, 0.f);
                    }
                }
#pragma unroll
                for (int off = 16; off >= 4; off >>= 1) {
                    s0 += __shfl_down_sync(0xFFFFFFFFu, s0, off);
                    s1 += __shfl_down_sync(0xFFFFFFFFu, s1, off);
                }
                if (lane < 4) {
                    const int colw = wc * 40 + nt * 8 + lane * 2;
                    if (colw < DH) {
                        const int mol = molBase + (mtb >> 1);
                        float2 v;
                        v.x = s0 * 0.03125f;
                        v.y = s1 * 0.03125f;
                        *(float2*)&dOut[(size_t)mol * OUTC + colw] = v;
                    }
                }
            }
        }
    } else {
        __half* __restrict__ OUTp = (MODE == 1) ? g_inph : g_h2h;
        const int crow = lane >> 2, cc0 = (lane & 3) * 2;
#pragma unroll
        for (int mt = 0; mt < 4; mt++) {
#pragma unroll
            for (int nt = 0; nt < 5; nt++) {
                const int col = wc * 40 + nt * 8 + cc0;
                if (col >= DH) continue;
#pragma unroll
                for (int half = 0; half < 2; half++) {
                    const int grow = rowBase + wr * 64 + mt * 16 + crow + half * 8;
                    const size_t o = (size_t)grow * SROW + col;
                    float v0 = acc[mt][nt][half * 2];
                    float v1 = acc[mt][nt][half * 2 + 1];
                    if (MODE == 2) {
                        float2 pv = __half22float2(*(const __half2*)&g_inph[o]);
                        v0 = fmaxf(pv.x + v0, 0.f);
                        v1 = fmaxf(pv.y + v1, 0.f);
                    }
                    *(__half2*)&OUTp[o] = __floats2half2_rn(v0, v1);
                }
            }
        }
    }
}

// ---------------- global-feature concat ----------------
__global__ void glob_copy(const float* __restrict__ g, float* __restrict__ out) {
    int idx = blockIdx.x * 256 + threadIdx.x;
    if (idx >= NM * 32) return;
    int mol = idx >> 5, j4 = idx & 31;
    float4 v = ((const float4*)g)[mol * 32 + j4];
    *(float4*)&out[(size_t)mol * OUTC + 300 + 4 * j4] = v;
}

// ---------------- launch ----------------
extern "C" void kernel_launch(void* const* d_in, const int* in_sizes, int n_in,
                              void* d_out, int out_size) {
    const float* atom_features   = (const float*)d_in[0];
    const float* f_ini           = (const float*)d_in[1];
    const float* global_features = (const float*)d_in[2];
    const float* W_i             = (const float*)d_in[3];
    const float* W_h             = (const float*)d_in[4];
    const float* W_o             = (const float*)d_in[5];
    const float* b_o             = (const float*)d_in[6];
    const int*   a2ib            = (const int*)d_in[7];
    const int*   mapping         = (const int*)d_in[8];
    float* out = (float*)d_out;

    static bool cfg = false;
    if (!cfg) {
        cudaFuncSetAttribute(mm_f16<1, KP1>, cudaFuncAttributeMaxDynamicSharedMemorySize, SMTOT);
        cudaFuncSetAttribute(mm_f16<2, KP2>, cudaFuncAttributeMaxDynamicSharedMemorySize, SMTOT);
        cudaFuncSetAttribute(mm_f16<3, KP3>, cudaFuncAttributeMaxDynamicSharedMemorySize, SMTOT);
        cfg = true;
    }

    glob_copy<<<(NM * 32 + 255) / 256, 256>>>(global_features, out);
    prep_all<<<(320 * (KP1 + KP2 + KP3) + 255) / 256, 256>>>(W_i, W_h, W_o);

    // 1) inp = f_ini @ W_i  (stored fp16, stride 304)
    mm_f16<1, KP1><<<NB / 128, 512, SMTOT>>>(f_ini, nullptr, nullptr);
    // 2) m1 = sum relu(inp[mapping])        [half2 math, uint4 IO]
    gather_relu<<<(NB * SR4 + 255) / 256, 256>>>(mapping);
    // 3) m2 = sum m1[mapping]
    gather2<<<(NB * SR4 + 255) / 256, 256>>>(mapping);
    // 4) h2 = relu(inp + m2 @ W_h)
    mm_f16<2, KP2><<<NB / 128, 512, SMTOT>>>(nullptr, nullptr, nullptr);
    // 5) msgs = sum h2[a2ib]
    gather_atom<<<(NA * SR4 + 255) / 256, 256>>>(a2ib);
    // 6+7) out = mean(relu([atomF | msgs] @ W_o + b_o))   [readout fused]
    mm_f16<3, KP3><<<NA / 128, 512, SMTOT>>>(atom_features, b_o, out);
}

// round 12
// speedup vs baseline: 2.9827x; 1.0130x over previous
#include <cuda_runtime.h>
#include <cuda_fp16.h>
#include <cstdint>

#define NB 131072
#define NA 65536
#define NM 2048
#define DH 300
#define AF 133
#define K1 147
#define GF 128
#define OUTC 428

#define KP1 160
#define KP2 320
#define KP3 448

#define SROW 304            // padded intermediate row stride (halves)
#define SR4  38             // uint4 per row
#define GC   19             // column-chunks per gather thread pair (2x uint4)

// ---------------- device scratch ----------------
__device__ __align__(16) __half g_W1[320 * KP1];
__device__ __align__(16) __half g_W2[320 * KP2];
__device__ __align__(16) __half g_W3[320 * KP3];
__device__ __align__(16) __half g_inph [(size_t)NB * SROW];
__device__ __align__(16) __half g_m1h  [(size_t)NB * SROW];
__device__ __align__(16) __half g_m2h  [(size_t)NB * KP2];   // cols 304..319 stay 0
__device__ __align__(16) __half g_h2h  [(size_t)NB * SROW];
__device__ __align__(16) __half g_msgsh[(size_t)NA * SROW];

// ---------------- helpers ----------------
__device__ __forceinline__ uint32_t s2u(const void* p) {
    uint32_t a;
    asm("{ .reg .u64 t; cvta.to.shared.u64 t, %1; cvt.u32.u64 %0, t; }"
        : "=r"(a) : "l"(p));
    return a;
}
__device__ __forceinline__ void cpa16(uint32_t s, const void* g) {
    asm volatile("cp.async.cg.shared.global [%0], [%1], 16;" :: "r"(s), "l"(g));
}
#define CP_COMMIT() asm volatile("cp.async.commit_group;" ::: "memory")
#define CP_WAIT1()  asm volatile("cp.async.wait_group 1;" ::: "memory")

__device__ __forceinline__ void ldmx4(uint32_t* r, uint32_t a) {
    asm volatile("ldmatrix.sync.aligned.m8n8.x4.shared.b16 {%0,%1,%2,%3}, [%4];"
                 : "=r"(r[0]), "=r"(r[1]), "=r"(r[2]), "=r"(r[3]) : "r"(a));
}
__device__ __forceinline__ void ldmx2(uint32_t* r, uint32_t a) {
    asm volatile("ldmatrix.sync.aligned.m8n8.x2.shared.b16 {%0,%1}, [%2];"
                 : "=r"(r[0]), "=r"(r[1]) : "r"(a));
}
__device__ __forceinline__ void mma_f16(float* c, const uint32_t* a, const uint32_t* b) {
    asm volatile(
        "mma.sync.aligned.m16n8k16.row.col.f32.f16.f16.f32 "
        "{%0,%1,%2,%3}, {%4,%5,%6,%7}, {%8,%9}, {%0,%1,%2,%3};"
        : "+f"(c[0]), "+f"(c[1]), "+f"(c[2]), "+f"(c[3])
        : "r"(a[0]), "r"(a[1]), "r"(a[2]), "r"(a[3]), "r"(b[0]), "r"(b[1]));
}
__device__ __forceinline__ __half2 u2h(uint32_t u) { return *(__half2*)&u; }
__device__ __forceinline__ uint32_t h2u(__half2 h) { return *(uint32_t*)&h; }

__device__ __forceinline__ uint32_t rsum4(uint32_t a, uint32_t b, uint32_t c, uint32_t d) {
    const __half2 z = __float2half2_rn(0.f);
    __half2 r = __hadd2(__hadd2(__hmax2(u2h(a), z), __hmax2(u2h(b), z)),
                        __hadd2(__hmax2(u2h(c), z), __hmax2(u2h(d), z)));
    return h2u(r);
}
__device__ __forceinline__ uint32_t sum4(uint32_t a, uint32_t b, uint32_t c, uint32_t d) {
    __half2 r = __hadd2(__hadd2(u2h(a), u2h(b)), __hadd2(u2h(c), u2h(d)));
    return h2u(r);
}
__device__ __forceinline__ uint4 rsum16(uint4 a, uint4 b, uint4 c, uint4 d) {
    uint4 o;
    o.x = rsum4(a.x, b.x, c.x, d.x);
    o.y = rsum4(a.y, b.y, c.y, d.y);
    o.z = rsum4(a.z, b.z, c.z, d.z);
    o.w = rsum4(a.w, b.w, c.w, d.w);
    return o;
}
__device__ __forceinline__ uint4 sum16(uint4 a, uint4 b, uint4 c, uint4 d) {
    uint4 o;
    o.x = sum4(a.x, b.x, c.x, d.x);
    o.y = sum4(a.y, b.y, c.y, d.y);
    o.z = sum4(a.z, b.z, c.z, d.z);
    o.w = sum4(a.w, b.w, c.w, d.w);
    return o;
}

// ---------------- weight prep (one launch for all 3) ----------------
__global__ void prep_all(const float* __restrict__ W1s,
                         const float* __restrict__ W2s,
                         const float* __restrict__ W3s) {
    int idx = blockIdx.x * 256 + threadIdx.x;
    const int T1 = 320 * KP1, T2 = 320 * KP2;
    const float* W;
    __half* B;
    int KP, mode;
    if (idx < T1) { W = W1s; B = g_W1; KP = KP1; mode = 1; }
    else if (idx < T1 + T2) { idx -= T1; W = W2s; B = g_W2; KP = KP2; mode = 2; }
    else {
        idx -= T1 + T2;
        if (idx >= 320 * KP3) return;
        W = W3s; B = g_W3; KP = KP3; mode = 3;
    }
    int n = idx / KP, k = idx % KP;
    int src;
    if (mode == 3) src = (k < 133) ? k : (k >= 136 && k < 436) ? k - 3 : -1;
    else if (mode == 1) src = (k < K1) ? k : -1;
    else src = (k < DH) ? k : -1;
    float v = (n < 300 && src >= 0) ? W[src * 300 + n] : 0.f;
    B[(size_t)n * KP + k] = __float2half_rn(v);
}

// ---------------- gather1: m1h = sum_j relu(inph[map[j]])  (2 uint4/thread) ----
__global__ void gather_relu(const int* __restrict__ map) {
    int idx = blockIdx.x * 256 + threadIdx.x;
    if (idx >= NB * GC) return;
    int r = idx / GC, c = idx % GC;
    int4 m = ((const int4*)map)[r];
    const uint4* S = (const uint4*)g_inph;
    const size_t bx = (size_t)m.x * SR4 + c, by = (size_t)m.y * SR4 + c;
    const size_t bz = (size_t)m.z * SR4 + c, bw = (size_t)m.w * SR4 + c;
    uint4 a0 = S[bx],      b0 = S[by],      c0 = S[bz],      d0 = S[bw];
    uint4 a1 = S[bx + GC], b1 = S[by + GC], c1 = S[bz + GC], d1 = S[bw + GC];
    uint4* D = (uint4*)g_m1h;
    D[(size_t)r * SR4 + c]      = rsum16(a0, b0, c0, d0);
    D[(size_t)r * SR4 + c + GC] = rsum16(a1, b1, c1, d1);
}

// ---------------- gather2: m2h = sum_j m1h[map[j]] -> [NB x 320] ----------------
__global__ void gather2(const int* __restrict__ map) {
    int idx = blockIdx.x * 256 + threadIdx.x;
    if (idx >= NB * GC) return;
    int r = idx / GC, c = idx % GC;
    int4 m = ((const int4*)map)[r];
    const uint4* S = (const uint4*)g_m1h;
    const size_t bx = (size_t)m.x * SR4 + c, by = (size_t)m.y * SR4 + c;
    const size_t bz = (size_t)m.z * SR4 + c, bw = (size_t)m.w * SR4 + c;
    uint4 a0 = S[bx],      b0 = S[by],      c0 = S[bz],      d0 = S[bw];
    uint4 a1 = S[bx + GC], b1 = S[by + GC], c1 = S[bz + GC], d1 = S[bw + GC];
    *(uint4*)&g_m2h[(size_t)r * KP2 + c * 8]        = sum16(a0, b0, c0, d0);
    *(uint4*)&g_m2h[(size_t)r * KP2 + (c + GC) * 8] = sum16(a1, b1, c1, d1);
}

// ---------------- gather_atom: msgs = sum_j h2h[a2ib[j]] ----------------
__global__ void gather_atom(const int* __restrict__ a2ib) {
    int idx = blockIdx.x * 256 + threadIdx.x;
    if (idx >= NA * GC) return;
    int r = idx / GC, c = idx % GC;
    int4 m = ((const int4*)a2ib)[r];
    const uint4* S = (const uint4*)g_h2h;
    const size_t bx = (size_t)m.x * SR4 + c, by = (size_t)m.y * SR4 + c;
    const size_t bz = (size_t)m.z * SR4 + c, bw = (size_t)m.w * SR4 + c;
    uint4 a0 = S[bx],      b0 = S[by],      c0 = S[bz],      d0 = S[bw];
    uint4 a1 = S[bx + GC], b1 = S[by + GC], c1 = S[bz + GC], d1 = S[bw + GC];
    uint4* D = (uint4*)g_msgsh;
    D[(size_t)r * SR4 + c]      = sum16(a0, b0, c0, d0);
    D[(size_t)r * SR4 + c + GC] = sum16(a1, b1, c1, d1);
}

// ---------------- FP16 GEMM: BM=128, BN=320, BK=32, 512 thr, 3 stages ----------------
#define BOFF  10240                 // A: 128*80
#define STG   (BOFF + 320 * 80)     // + B: 25600 -> 35840
#define SMTOT (3 * STG)             // 107520

template <int MODE, int KP>
__global__ void __launch_bounds__(512)
mm_f16(const float* __restrict__ srcA,
       const float* __restrict__ bias, float* __restrict__ dOut) {
    constexpr int NCH = KP / 32;
    const __half* __restrict__ Wt = (MODE == 1) ? g_W1 : (MODE == 2) ? g_W2 : g_W3;

    extern __shared__ __align__(16) char smem[];
    const uint32_t sb = s2u(smem);
    const int tid = threadIdx.x, w = tid >> 5, lane = tid & 31;
    const int wr = w & 1, wc = w >> 1;       // warp tile 64x40
    const int rowBase = blockIdx.x * 128;

    float acc[4][5][4];
#pragma unroll
    for (int i = 0; i < 4; i++)
#pragma unroll
        for (int j = 0; j < 5; j++)
#pragma unroll
            for (int q = 0; q < 4; q++) acc[i][j][q] = 0.f;

    // ---- A producer (MODE 1/3): warp owns 8 rows, lane owns one k column ----
    __half rbuf[8];
    auto loadA_regs = [&](int c) {
        const int k = c * 32 + lane;
#pragma unroll
        for (int i = 0; i < 8; i++) {
            const int grow = rowBase + w * 8 + i;
            __half v = __float2half_rn(0.f);
            if (MODE == 1) {
                if (k < K1) v = __float2half_rn(srcA[(size_t)grow * K1 + k]);
            } else if (MODE == 3) {
                if (k < AF) v = __float2half_rn(srcA[(size_t)grow * AF + k]);
                else if (k >= 136 && k < 436) v = g_msgsh[(size_t)grow * SROW + (k - 136)];
            }
            rbuf[i] = v;
        }
    };
    auto stsA = [&](int st) {
        char* p = smem + st * STG + (w * 8) * 80 + lane * 2;
#pragma unroll
        for (int i = 0; i < 8; i++) *(__half*)(p + i * 80) = rbuf[i];
    };

    // ---- A via cp.async (MODE 2): 128 rows x 4 segs = 512 = 1/thread ----
    auto cpA = [&](int c, int st) {
        const int row = tid >> 2, seg = tid & 3;
        cpa16(sb + st * STG + row * 80 + seg * 16,
              g_m2h + (size_t)(rowBase + row) * KP2 + c * 32 + seg * 8);
    };
    // ---- B: 320 rows x 4 segs = 1280 ----
    auto loadB = [&](int c, int st) {
#pragma unroll
        for (int i = tid; i < 1280; i += 512) {
            const int row = i >> 2, seg = i & 3;
            cpa16(sb + st * STG + BOFF + row * 80 + seg * 16,
                  Wt + (size_t)row * KP + c * 32 + seg * 8);
        }
    };

    // ---- prologue ----
    if (MODE != 2) {
        loadA_regs(0); stsA(0); loadB(0, 0); CP_COMMIT();
        loadA_regs(1); stsA(1); loadB(1, 1); CP_COMMIT();
        loadA_regs(2);
    } else {
        cpA(0, 0); loadB(0, 0); CP_COMMIT();
        cpA(1, 1); loadB(1, 1); CP_COMMIT();
    }

    // ldmatrix bases (80 B rows)
    const uint32_t aOff = (uint32_t)(wr * 64 + (lane & 15)) * 80
                        + (uint32_t)(lane >> 4) * 16;
    const int bl = lane & 15;
    const uint32_t bOff = BOFF + (uint32_t)(wc * 40 + (bl & 7)) * 80
                        + (uint32_t)(bl >> 3) * 16;

    for (int c = 0; c < NCH; c++) {
        CP_WAIT1();
        __syncthreads();
        if (c + 2 < NCH) {
            const int st = (c + 2) % 3;
            if (MODE != 2) { stsA(st); }
            else          { cpA(c + 2, st); }
            loadB(c + 2, st);
        }
        CP_COMMIT();
        if (MODE != 2 && c + 3 < NCH) loadA_regs(c + 3);

        const uint32_t stp = sb + (c % 3) * STG;
#pragma unroll
        for (int kh = 0; kh < 2; kh++) {
            uint32_t af[4][4], bf[5][2];
#pragma unroll
            for (int mt = 0; mt < 4; mt++)
                ldmx4(af[mt], stp + aOff + mt * (16 * 80) + kh * 32);
#pragma unroll
            for (int nt = 0; nt < 5; nt++)
                ldmx2(bf[nt], stp + bOff + nt * (8 * 80) + kh * 32);
#pragma unroll
            for (int mt = 0; mt < 4; mt++)
#pragma unroll
                for (int nt = 0; nt < 5; nt++)
                    mma_f16(acc[mt][nt], af[mt], bf[nt]);
        }
    }

    if (MODE == 3) {
        // fused per-molecule mean readout: 128 rows = 4 molecules
        const int molBase = blockIdx.x * 4 + wr * 2;
#pragma unroll
        for (int mtb = 0; mtb < 4; mtb += 2) {
#pragma unroll
            for (int nt = 0; nt < 5; nt++) {
                const int col2 = wc * 40 + nt * 8 + (lane & 3) * 2;
                float b0 = 0.f, b1 = 0.f;
                if (col2 < DH) { b0 = bias[col2]; b1 = bias[col2 + 1]; }
                float s0 = 0.f, s1 = 0.f;
#pragma unroll
                for (int p = 0; p < 2; p++) {
#pragma unroll
                    for (int h = 0; h < 2; h++) {
                        s0 += fmaxf(acc[mtb + p][nt][h * 2]     + b0, 0.f);
                        s1 += fmaxf(acc[mtb + p][nt][h * 2 + 1] + b1, 0.f);
                    }
                }
#pragma unroll
                for (int off = 16; off >= 4; off >>= 1) {
                    s0 += __shfl_down_sync(0xFFFFFFFFu, s0, off);
                    s1 += __shfl_down_sync(0xFFFFFFFFu, s1, off);
                }
                if (lane < 4) {
                    const int colw = wc * 40 + nt * 8 + lane * 2;
                    if (colw < DH) {
                        const int mol = molBase + (mtb >> 1);
                        float2 v;
                        v.x = s0 * 0.03125f;
                        v.y = s1 * 0.03125f;
                        *(float2*)&dOut[(size_t)mol * OUTC + colw] = v;
                    }
                }
            }
        }
    } else {
        __half* __restrict__ OUTp = (MODE == 1) ? g_inph : g_h2h;
        const int crow = lane >> 2, cc0 = (lane & 3) * 2;
#pragma unroll
        for (int mt = 0; mt < 4; mt++) {
#pragma unroll
            for (int nt = 0; nt < 5; nt++) {
                const int col = wc * 40 + nt * 8 + cc0;
                if (col >= DH) continue;
#pragma unroll
                for (int half = 0; half < 2; half++) {
                    const int grow = rowBase + wr * 64 + mt * 16 + crow + half * 8;
                    const size_t o = (size_t)grow * SROW + col;
                    float v0 = acc[mt][nt][half * 2];
                    float v1 = acc[mt][nt][half * 2 + 1];
                    if (MODE == 2) {
                        float2 pv = __half22float2(*(const __half2*)&g_inph[o]);
                        v0 = fmaxf(pv.x + v0, 0.f);
                        v1 = fmaxf(pv.y + v1, 0.f);
                    }
                    *(__half2*)&OUTp[o] = __floats2half2_rn(v0, v1);
                }
            }
        }
    }
}

// ---------------- global-feature concat ----------------
__global__ void glob_copy(const float* __restrict__ g, float* __restrict__ out) {
    int idx = blockIdx.x * 256 + threadIdx.x;
    if (idx >= NM * 32) return;
    int mol = idx >> 5, j4 = idx & 31;
    float4 v = ((const float4*)g)[mol * 32 + j4];
    *(float4*)&out[(size_t)mol * OUTC + 300 + 4 * j4] = v;
}

// ---------------- launch ----------------
extern "C" void kernel_launch(void* const* d_in, const int* in_sizes, int n_in,
                              void* d_out, int out_size) {
    const float* atom_features   = (const float*)d_in[0];
    const float* f_ini           = (const float*)d_in[1];
    const float* global_features = (const float*)d_in[2];
    const float* W_i             = (const float*)d_in[3];
    const float* W_h             = (const float*)d_in[4];
    const float* W_o             = (const float*)d_in[5];
    const float* b_o             = (const float*)d_in[6];
    const int*   a2ib            = (const int*)d_in[7];
    const int*   mapping         = (const int*)d_in[8];
    float* out = (float*)d_out;

    static bool cfg = false;
    if (!cfg) {
        cudaFuncSetAttribute(mm_f16<1, KP1>, cudaFuncAttributeMaxDynamicSharedMemorySize, SMTOT);
        cudaFuncSetAttribute(mm_f16<2, KP2>, cudaFuncAttributeMaxDynamicSharedMemorySize, SMTOT);
        cudaFuncSetAttribute(mm_f16<3, KP3>, cudaFuncAttributeMaxDynamicSharedMemorySize, SMTOT);
        cfg = true;
    }

    glob_copy<<<(NM * 32 + 255) / 256, 256>>>(global_features, out);
    prep_all<<<(320 * (KP1 + KP2 + KP3) + 255) / 256, 256>>>(W_i, W_h, W_o);

    // 1) inp = f_ini @ W_i  (stored fp16, stride 304)
    mm_f16<1, KP1><<<NB / 128, 512, SMTOT>>>(f_ini, nullptr, nullptr);
    // 2) m1 = sum relu(inp[mapping])        [2 uint4 per thread, MLP=8]
    gather_relu<<<(NB * GC + 255) / 256, 256>>>(mapping);
    // 3) m2 = sum m1[mapping]
    gather2<<<(NB * GC + 255) / 256, 256>>>(mapping);
    // 4) h2 = relu(inp + m2 @ W_h)
    mm_f16<2, KP2><<<NB / 128, 512, SMTOT>>>(nullptr, nullptr, nullptr);
    // 5) msgs = sum h2[a2ib]
    gather_atom<<<(NA * GC + 255) / 256, 256>>>(a2ib);
    // 6+7) out = mean(relu([atomF | msgs] @ W_o + b_o))   [readout fused]
    mm_f16<3, KP3><<<NA / 128, 512, SMTOT>>>(atom_features, b_o, out);
}

// round 14
// speedup vs baseline: 2.9957x; 1.0043x over previous
#include <cuda_runtime.h>
#include <cuda_fp16.h>
#include <cstdint>

#define NB 131072
#define NA 65536
#define NM 2048
#define DH 300
#define AF 133
#define K1 147
#define GF 128
#define OUTC 428

#define KP1 160
#define KP2 320
#define KP3 448

#define SROW 304            // padded intermediate row stride (halves)
#define SR8  19             // 32B chunks per row (608 B)

struct U8 { uint4 a, b; };

// ---------------- device scratch ----------------
__device__ __align__(32) __half g_W1[320 * KP1];
__device__ __align__(32) __half g_W2[320 * KP2];
__device__ __align__(32) __half g_W3[320 * KP3];
__device__ __align__(32) __half g_inph [(size_t)NB * SROW];
__device__ __align__(32) __half g_m1h  [(size_t)NB * SROW];
__device__ __align__(32) __half g_m2h  [(size_t)NB * KP2];   // cols 304..319 stay 0
__device__ __align__(32) __half g_h2h  [(size_t)NB * SROW];
__device__ __align__(32) __half g_msgsh[(size_t)NA * SROW];

// ---------------- helpers ----------------
__device__ __forceinline__ uint32_t s2u(const void* p) {
    uint32_t a;
    asm("{ .reg .u64 t; cvta.to.shared.u64 t, %1; cvt.u32.u64 %0, t; }"
        : "=r"(a) : "l"(p));
    return a;
}
__device__ __forceinline__ void cpa16(uint32_t s, const void* g) {
    asm volatile("cp.async.cg.shared.global [%0], [%1], 16;" :: "r"(s), "l"(g));
}
#define CP_COMMIT() asm volatile("cp.async.commit_group;" ::: "memory")
#define CP_WAIT1()  asm volatile("cp.async.wait_group 1;" ::: "memory")

__device__ __forceinline__ void ldmx4(uint32_t* r, uint32_t a) {
    asm volatile("ldmatrix.sync.aligned.m8n8.x4.shared.b16 {%0,%1,%2,%3}, [%4];"
                 : "=r"(r[0]), "=r"(r[1]), "=r"(r[2]), "=r"(r[3]) : "r"(a));
}
__device__ __forceinline__ void ldmx2(uint32_t* r, uint32_t a) {
    asm volatile("ldmatrix.sync.aligned.m8n8.x2.shared.b16 {%0,%1}, [%2];"
                 : "=r"(r[0]), "=r"(r[1]) : "r"(a));
}
__device__ __forceinline__ void mma_f16(float* c, const uint32_t* a, const uint32_t* b) {
    asm volatile(
        "mma.sync.aligned.m16n8k16.row.col.f32.f16.f16.f32 "
        "{%0,%1,%2,%3}, {%4,%5,%6,%7}, {%8,%9}, {%0,%1,%2,%3};"
        : "+f"(c[0]), "+f"(c[1]), "+f"(c[2]), "+f"(c[3])
        : "r"(a[0]), "r"(a[1]), "r"(a[2]), "r"(a[3]), "r"(b[0]), "r"(b[1]));
}
__device__ __forceinline__ __half2 u2h(uint32_t u) { return *(__half2*)&u; }
__device__ __forceinline__ uint32_t h2u(__half2 h) { return *(uint32_t*)&h; }

// 32-byte L2 residency-hinted IO (v8.b32 required for hints on this target)
__device__ __forceinline__ U8 ldg32_el(const __half* p) {
    U8 v;
    asm volatile("ld.global.nc.L2::evict_last.v8.b32 {%0,%1,%2,%3,%4,%5,%6,%7}, [%8];"
                 : "=r"(v.a.x), "=r"(v.a.y), "=r"(v.a.z), "=r"(v.a.w),
                   "=r"(v.b.x), "=r"(v.b.y), "=r"(v.b.z), "=r"(v.b.w) : "l"(p));
    return v;
}
__device__ __forceinline__ void stg32_ef(__half* p, U8 v) {
    asm volatile("st.global.L2::evict_first.v8.b32 [%0], {%1,%2,%3,%4,%5,%6,%7,%8};"
                 :: "l"(p), "r"(v.a.x), "r"(v.a.y), "r"(v.a.z), "r"(v.a.w),
                    "r"(v.b.x), "r"(v.b.y), "r"(v.b.z), "r"(v.b.w) : "memory");
}

__device__ __forceinline__ uint32_t rsum4(uint32_t a, uint32_t b, uint32_t c, uint32_t d) {
    const __half2 z = __float2half2_rn(0.f);
    __half2 r = __hadd2(__hadd2(__hmax2(u2h(a), z), __hmax2(u2h(b), z)),
                        __hadd2(__hmax2(u2h(c), z), __hmax2(u2h(d), z)));
    return h2u(r);
}
__device__ __forceinline__ uint32_t sum4(uint32_t a, uint32_t b, uint32_t c, uint32_t d) {
    __half2 r = __hadd2(__hadd2(u2h(a), u2h(b)), __hadd2(u2h(c), u2h(d)));
    return h2u(r);
}
__device__ __forceinline__ uint4 rsum16(uint4 a, uint4 b, uint4 c, uint4 d) {
    uint4 o;
    o.x = rsum4(a.x, b.x, c.x, d.x);
    o.y = rsum4(a.y, b.y, c.y, d.y);
    o.z = rsum4(a.z, b.z, c.z, d.z);
    o.w = rsum4(a.w, b.w, c.w, d.w);
    return o;
}
__device__ __forceinline__ uint4 sum16(uint4 a, uint4 b, uint4 c, uint4 d) {
    uint4 o;
    o.x = sum4(a.x, b.x, c.x, d.x);
    o.y = sum4(a.y, b.y, c.y, d.y);
    o.z = sum4(a.z, b.z, c.z, d.z);
    o.w = sum4(a.w, b.w, c.w, d.w);
    return o;
}
__device__ __forceinline__ U8 rsum32(U8 a, U8 b, U8 c, U8 d) {
    U8 o;
    o.a = rsum16(a.a, b.a, c.a, d.a);
    o.b = rsum16(a.b, b.b, c.b, d.b);
    return o;
}
__device__ __forceinline__ U8 sum32(U8 a, U8 b, U8 c, U8 d) {
    U8 o;
    o.a = sum16(a.a, b.a, c.a, d.a);
    o.b = sum16(a.b, b.b, c.b, d.b);
    return o;
}

// ---------------- weight prep (one launch for all 3) ----------------
__global__ void prep_all(const float* __restrict__ W1s,
                         const float* __restrict__ W2s,
                         const float* __restrict__ W3s) {
    int idx = blockIdx.x * 256 + threadIdx.x;
    const int T1 = 320 * KP1, T2 = 320 * KP2;
    const float* W;
    __half* B;
    int KP, mode;
    if (idx < T1) { W = W1s; B = g_W1; KP = KP1; mode = 1; }
    else if (idx < T1 + T2) { idx -= T1; W = W2s; B = g_W2; KP = KP2; mode = 2; }
    else {
        idx -= T1 + T2;
        if (idx >= 320 * KP3) return;
        W = W3s; B = g_W3; KP = KP3; mode = 3;
    }
    int n = idx / KP, k = idx % KP;
    int src;
    if (mode == 3) src = (k < 133) ? k : (k >= 136 && k < 436) ? k - 3 : -1;
    else if (mode == 1) src = (k < K1) ? k : -1;
    else src = (k < DH) ? k : -1;
    float v = (n < 300 && src >= 0) ? W[src * 300 + n] : 0.f;
    B[(size_t)n * KP + k] = __float2half_rn(v);
}

// ---------------- gather1: m1h = sum_j relu(inph[map[j]])  (32B chunks) ----
__global__ void gather_relu(const int* __restrict__ map) {
    int idx = blockIdx.x * 256 + threadIdx.x;
    if (idx >= NB * SR8) return;
    int r = idx / SR8, c = idx % SR8;
    int4 m = ((const int4*)map)[r];
    const int co = c * 16;   // half offset of 32B chunk
    U8 a = ldg32_el(g_inph + (size_t)m.x * SROW + co);
    U8 b = ldg32_el(g_inph + (size_t)m.y * SROW + co);
    U8 cc = ldg32_el(g_inph + (size_t)m.z * SROW + co);
    U8 d = ldg32_el(g_inph + (size_t)m.w * SROW + co);
    stg32_ef(g_m1h + (size_t)r * SROW + co, rsum32(a, b, cc, d));
}

// ---------------- gather2: m2h = sum_j m1h[map[j]] -> [NB x 320] ----------------
__global__ void gather2(const int* __restrict__ map) {
    int idx = blockIdx.x * 256 + threadIdx.x;
    if (idx >= NB * SR8) return;
    int r = idx / SR8, c = idx % SR8;
    int4 m = ((const int4*)map)[r];
    const int co = c * 16;
    U8 a = ldg32_el(g_m1h + (size_t)m.x * SROW + co);
    U8 b = ldg32_el(g_m1h + (size_t)m.y * SROW + co);
    U8 cc = ldg32_el(g_m1h + (size_t)m.z * SROW + co);
    U8 d = ldg32_el(g_m1h + (size_t)m.w * SROW + co);
    stg32_ef(g_m2h + (size_t)r * KP2 + co, sum32(a, b, cc, d));
}

// ---------------- gather_atom: msgs = sum_j h2h[a2ib[j]] ----------------
__global__ void gather_atom(const int* __restrict__ a2ib) {
    int idx = blockIdx.x * 256 + threadIdx.x;
    if (idx >= NA * SR8) return;
    int r = idx / SR8, c = idx % SR8;
    int4 m = ((const int4*)a2ib)[r];
    const int co = c * 16;
    U8 a = ldg32_el(g_h2h + (size_t)m.x * SROW + co);
    U8 b = ldg32_el(g_h2h + (size_t)m.y * SROW + co);
    U8 cc = ldg32_el(g_h2h + (size_t)m.z * SROW + co);
    U8 d = ldg32_el(g_h2h + (size_t)m.w * SROW + co);
    stg32_ef(g_msgsh + (size_t)r * SROW + co, sum32(a, b, cc, d));
}

// ---------------- FP16 GEMM: BM=128, BN=320, BK=32, 512 thr, 3 stages ----------------
#define BOFF  10240                 // A: 128*80
#define STG   (BOFF + 320 * 80)     // + B: 25600 -> 35840
#define SMTOT (3 * STG)             // 107520

template <int MODE, int KP>
__global__ void __launch_bounds__(512)
mm_f16(const float* __restrict__ srcA,
       const float* __restrict__ bias, float* __restrict__ dOut) {
    constexpr int NCH = KP / 32;
    const __half* __restrict__ Wt = (MODE == 1) ? g_W1 : (MODE == 2) ? g_W2 : g_W3;

    extern __shared__ __align__(16) char smem[];
    const uint32_t sb = s2u(smem);
    const int tid = threadIdx.x, w = tid >> 5, lane = tid & 31;
    const int wr = w & 1, wc = w >> 1;       // warp tile 64x40
    const int rowBase = blockIdx.x * 128;

    float acc[4][5][4];
#pragma unroll
    for (int i = 0; i < 4; i++)
#pragma unroll
        for (int j = 0; j < 5; j++)
#pragma unroll
            for (int q = 0; q < 4; q++) acc[i][j][q] = 0.f;

    // ---- A producer (MODE 1/3): warp owns 8 rows, lane owns one k column ----
    __half rbuf[8];
    auto loadA_regs = [&](int c) {
        const int k = c * 32 + lane;
#pragma unroll
        for (int i = 0; i < 8; i++) {
            const int grow = rowBase + w * 8 + i;
            __half v = __float2half_rn(0.f);
            if (MODE == 1) {
                if (k < K1) v = __float2half_rn(srcA[(size_t)grow * K1 + k]);
            } else if (MODE == 3) {
                if (k < AF) v = __float2half_rn(srcA[(size_t)grow * AF + k]);
                else if (k >= 136 && k < 436) v = g_msgsh[(size_t)grow * SROW + (k - 136)];
            }
            rbuf[i] = v;
        }
    };
    auto stsA = [&](int st) {
        char* p = smem + st * STG + (w * 8) * 80 + lane * 2;
#pragma unroll
        for (int i = 0; i < 8; i++) *(__half*)(p + i * 80) = rbuf[i];
    };

    // ---- A via cp.async (MODE 2): 128 rows x 4 segs = 512 = 1/thread ----
    auto cpA = [&](int c, int st) {
        const int row = tid >> 2, seg = tid & 3;
        cpa16(sb + st * STG + row * 80 + seg * 16,
              g_m2h + (size_t)(rowBase + row) * KP2 + c * 32 + seg * 8);
    };
    // ---- B: 320 rows x 4 segs = 1280 ----
    auto loadB = [&](int c, int st) {
#pragma unroll
        for (int i = tid; i < 1280; i += 512) {
            const int row = i >> 2, seg = i & 3;
            cpa16(sb + st * STG + BOFF + row * 80 + seg * 16,
                  Wt + (size_t)row * KP + c * 32 + seg * 8);
        }
    };

    // ---- prologue ----
    if (MODE != 2) {
        loadA_regs(0); stsA(0); loadB(0, 0); CP_COMMIT();
        loadA_regs(1); stsA(1); loadB(1, 1); CP_COMMIT();
        loadA_regs(2);
    } else {
        cpA(0, 0); loadB(0, 0); CP_COMMIT();
        cpA(1, 1); loadB(1, 1); CP_COMMIT();
    }

    // ldmatrix bases (80 B rows)
    const uint32_t aOff = (uint32_t)(wr * 64 + (lane & 15)) * 80
                        + (uint32_t)(lane >> 4) * 16;
    const int bl = lane & 15;
    const uint32_t bOff = BOFF + (uint32_t)(wc * 40 + (bl & 7)) * 80
                        + (uint32_t)(bl >> 3) * 16;

    for (int c = 0; c < NCH; c++) {
        CP_WAIT1();
        __syncthreads();
        if (c + 2 < NCH) {
            const int st = (c + 2) % 3;
            if (MODE != 2) { stsA(st); }
            else          { cpA(c + 2, st); }
            loadB(c + 2, st);
        }
        CP_COMMIT();
        if (MODE != 2 && c + 3 < NCH) loadA_regs(c + 3);

        const uint32_t stp = sb + (c % 3) * STG;
#pragma unroll
        for (int kh = 0; kh < 2; kh++) {
            uint32_t af[4][4], bf[5][2];
#pragma unroll
            for (int mt = 0; mt < 4; mt++)
                ldmx4(af[mt], stp + aOff + mt * (16 * 80) + kh * 32);
#pragma unroll
            for (int nt = 0; nt < 5; nt++)
                ldmx2(bf[nt], stp + bOff + nt * (8 * 80) + kh * 32);
#pragma unroll
            for (int mt = 0; mt < 4; mt++)
#pragma unroll
                for (int nt = 0; nt < 5; nt++)
                    mma_f16(acc[mt][nt], af[mt], bf[nt]);
        }
    }

    if (MODE == 3) {
        // fused per-molecule mean readout: 128 rows = 4 molecules
        const int molBase = blockIdx.x * 4 + wr * 2;
#pragma unroll
        for (int mtb = 0; mtb < 4; mtb += 2) {
#pragma unroll
            for (int nt = 0; nt < 5; nt++) {
                const int col2 = wc * 40 + nt * 8 + (lane & 3) * 2;
                float b0 = 0.f, b1 = 0.f;
                if (col2 < DH) { b0 = bias[col2]; b1 = bias[col2 + 1]; }
                float s0 = 0.f, s1 = 0.f;
#pragma unroll
                for (int p = 0; p < 2; p++) {
#pragma unroll
                    for (int h = 0; h < 2; h++) {
                        s0 += fmaxf(acc[mtb + p][nt][h * 2]     + b0, 0.f);
                        s1 += fmaxf(acc[mtb + p][nt][h * 2 + 1] + b1, 0.f);
                    }
                }
#pragma unroll
                for (int off = 16; off >= 4; off >>= 1) {
                    s0 += __shfl_down_sync(0xFFFFFFFFu, s0, off);
                    s1 += __shfl_down_sync(0xFFFFFFFFu, s1, off);
                }
                if (lane < 4) {
                    const int colw = wc * 40 + nt * 8 + lane * 2;
                    if (colw < DH) {
                        const int mol = molBase + (mtb >> 1);
                        float2 v;
                        v.x = s0 * 0.03125f;
                        v.y = s1 * 0.03125f;
                        *(float2*)&dOut[(size_t)mol * OUTC + colw] = v;
                    }
                }
            }
        }
    } else {
        __half* __restrict__ OUTp = (MODE == 1) ? g_inph : g_h2h;
        const int crow = lane >> 2, cc0 = (lane & 3) * 2;
#pragma unroll
        for (int mt = 0; mt < 4; mt++) {
#pragma unroll
            for (int nt = 0; nt < 5; nt++) {
                const int col = wc * 40 + nt * 8 + cc0;
                if (col >= DH) continue;
#pragma unroll
                for (int half = 0; half < 2; half++) {
                    const int grow = rowBase + wr * 64 + mt * 16 + crow + half * 8;
                    const size_t o = (size_t)grow * SROW + col;
                    float v0 = acc[mt][nt][half * 2];
                    float v1 = acc[mt][nt][half * 2 + 1];
                    if (MODE == 2) {
                        float2 pv = __half22float2(*(const __half2*)&g_inph[o]);
                        v0 = fmaxf(pv.x + v0, 0.f);
                        v1 = fmaxf(pv.y + v1, 0.f);
                    }
                    *(__half2*)&OUTp[o] = __floats2half2_rn(v0, v1);
                }
            }
        }
    }
}

// ---------------- global-feature concat ----------------
__global__ void glob_copy(const float* __restrict__ g, float* __restrict__ out) {
    int idx = blockIdx.x * 256 + threadIdx.x;
    if (idx >= NM * 32) return;
    int mol = idx >> 5, j4 = idx & 31;
    float4 v = ((const float4*)g)[mol * 32 + j4];
    *(float4*)&out[(size_t)mol * OUTC + 300 + 4 * j4] = v;
}

// ---------------- launch ----------------
extern "C" void kernel_launch(void* const* d_in, const int* in_sizes, int n_in,
                              void* d_out, int out_size) {
    const float* atom_features   = (const float*)d_in[0];
    const float* f_ini           = (const float*)d_in[1];
    const float* global_features = (const float*)d_in[2];
    const float* W_i             = (const float*)d_in[3];
    const float* W_h             = (const float*)d_in[4];
    const float* W_o             = (const float*)d_in[5];
    const float* b_o             = (const float*)d_in[6];
    const int*   a2ib            = (const int*)d_in[7];
    const int*   mapping         = (const int*)d_in[8];
    float* out = (float*)d_out;

    static bool cfg = false;
    if (!cfg) {
        cudaFuncSetAttribute(mm_f16<1, KP1>, cudaFuncAttributeMaxDynamicSharedMemorySize, SMTOT);
        cudaFuncSetAttribute(mm_f16<2, KP2>, cudaFuncAttributeMaxDynamicSharedMemorySize, SMTOT);
        cudaFuncSetAttribute(mm_f16<3, KP3>, cudaFuncAttributeMaxDynamicSharedMemorySize, SMTOT);
        cfg = true;
    }

    glob_copy<<<(NM * 32 + 255) / 256, 256>>>(global_features, out);
    prep_all<<<(320 * (KP1 + KP2 + KP3) + 255) / 256, 256>>>(W_i, W_h, W_o);

    // 1) inp = f_ini @ W_i  (stored fp16, stride 304)
    mm_f16<1, KP1><<<NB / 128, 512, SMTOT>>>(f_ini, nullptr, nullptr);
    // 2) m1 = sum relu(inp[mapping])        [32B hinted IO, evict_last sources]
    gather_relu<<<(NB * SR8 + 255) / 256, 256>>>(mapping);
    // 3) m2 = sum m1[mapping]               [evict_first stream-out]
    gather2<<<(NB * SR8 + 255) / 256, 256>>>(mapping);
    // 4) h2 = relu(inp + m2 @ W_h)
    mm_f16<2, KP2><<<NB / 128, 512, SMTOT>>>(nullptr, nullptr, nullptr);
    // 5) msgs = sum h2[a2ib]
    gather_atom<<<(NA * SR8 + 255) / 256, 256>>>(a2ib);
    // 6+7) out = mean(relu([atomF | msgs] @ W_o + b_o))   [readout fused]
    mm_f16<3, KP3><<<NA / 128, 512, SMTOT>>>(atom_features, b_o, out);
}

// round 15
// speedup vs baseline: 3.1176x; 1.0407x over previous
#include <cuda_runtime.h>
#include <cuda_fp16.h>
#include <cstdint>

#define NB 131072
#define NA 65536
#define NM 2048
#define DH 300
#define AF 133
#define K1 147
#define GF 128
#define OUTC 428

#define KP1 160
#define KP2 320
#define KP3 448

#define SROW 304            // padded intermediate row stride (halves)
#define SR8  19             // 32B chunks per row (608 B)

struct U8 { uint4 a, b; };

// ---------------- device scratch ----------------
__device__ __align__(32) __half g_W1[320 * KP1];
__device__ __align__(32) __half g_W2[320 * KP2];
__device__ __align__(32) __half g_W3[320 * KP3];
__device__ __align__(32) __half g_inph [(size_t)NB * SROW];
__device__ __align__(32) __half g_m1h  [(size_t)NB * SROW];
__device__ __align__(32) __half g_m2h  [(size_t)NB * KP2];   // cols 304..319 stay 0
__device__ __align__(32) __half g_h2h  [(size_t)NB * SROW];
__device__ __align__(32) __half g_msgsh[(size_t)NA * SROW];

// ---------------- helpers ----------------
__device__ __forceinline__ uint32_t s2u(const void* p) {
    uint32_t a;
    asm("{ .reg .u64 t; cvta.to.shared.u64 t, %1; cvt.u32.u64 %0, t; }"
        : "=r"(a) : "l"(p));
    return a;
}
__device__ __forceinline__ void cpa16(uint32_t s, const void* g) {
    asm volatile("cp.async.cg.shared.global [%0], [%1], 16;" :: "r"(s), "l"(g));
}
#define CP_COMMIT() asm volatile("cp.async.commit_group;" ::: "memory")
#define CP_WAIT1()  asm volatile("cp.async.wait_group 1;" ::: "memory")

__device__ __forceinline__ void ldmx4(uint32_t* r, uint32_t a) {
    asm volatile("ldmatrix.sync.aligned.m8n8.x4.shared.b16 {%0,%1,%2,%3}, [%4];"
                 : "=r"(r[0]), "=r"(r[1]), "=r"(r[2]), "=r"(r[3]) : "r"(a));
}
__device__ __forceinline__ void ldmx2(uint32_t* r, uint32_t a) {
    asm volatile("ldmatrix.sync.aligned.m8n8.x2.shared.b16 {%0,%1}, [%2];"
                 : "=r"(r[0]), "=r"(r[1]) : "r"(a));
}
__device__ __forceinline__ void mma_f16(float* c, const uint32_t* a, const uint32_t* b) {
    asm volatile(
        "mma.sync.aligned.m16n8k16.row.col.f32.f16.f16.f32 "
        "{%0,%1,%2,%3}, {%4,%5,%6,%7}, {%8,%9}, {%0,%1,%2,%3};"
        : "+f"(c[0]), "+f"(c[1]), "+f"(c[2]), "+f"(c[3])
        : "r"(a[0]), "r"(a[1]), "r"(a[2]), "r"(a[3]), "r"(b[0]), "r"(b[1]));
}
__device__ __forceinline__ __half2 u2h(uint32_t u) { return *(__half2*)&u; }
__device__ __forceinline__ uint32_t h2u(__half2 h) { return *(uint32_t*)&h; }

// 32-byte L2 residency-hinted IO (v8.b32 required for hints on this target)
__device__ __forceinline__ U8 ldg32_el(const __half* p) {
    U8 v;
    asm volatile("ld.global.nc.L2::evict_last.v8.b32 {%0,%1,%2,%3,%4,%5,%6,%7}, [%8];"
                 : "=r"(v.a.x), "=r"(v.a.y), "=r"(v.a.z), "=r"(v.a.w),
                   "=r"(v.b.x), "=r"(v.b.y), "=r"(v.b.z), "=r"(v.b.w) : "l"(p));
    return v;
}
__device__ __forceinline__ void stg32_ef(__half* p, U8 v) {
    asm volatile("st.global.L2::evict_first.v8.b32 [%0], {%1,%2,%3,%4,%5,%6,%7,%8};"
                 :: "l"(p), "r"(v.a.x), "r"(v.a.y), "r"(v.a.z), "r"(v.a.w),
                    "r"(v.b.x), "r"(v.b.y), "r"(v.b.z), "r"(v.b.w) : "memory");
}
// evict_last store: for buffers re-read multiple times (m1h)
__device__ __forceinline__ void stg32_el(__half* p, U8 v) {
    asm volatile("st.global.L2::evict_last.v8.b32 [%0], {%1,%2,%3,%4,%5,%6,%7,%8};"
                 :: "l"(p), "r"(v.a.x), "r"(v.a.y), "r"(v.a.z), "r"(v.a.w),
                    "r"(v.b.x), "r"(v.b.y), "r"(v.b.z), "r"(v.b.w) : "memory");
}

__device__ __forceinline__ uint32_t rsum4(uint32_t a, uint32_t b, uint32_t c, uint32_t d) {
    const __half2 z = __float2half2_rn(0.f);
    __half2 r = __hadd2(__hadd2(__hmax2(u2h(a), z), __hmax2(u2h(b), z)),
                        __hadd2(__hmax2(u2h(c), z), __hmax2(u2h(d), z)));
    return h2u(r);
}
__device__ __forceinline__ uint32_t sum4(uint32_t a, uint32_t b, uint32_t c, uint32_t d) {
    __half2 r = __hadd2(__hadd2(u2h(a), u2h(b)), __hadd2(u2h(c), u2h(d)));
    return h2u(r);
}
__device__ __forceinline__ uint4 rsum16(uint4 a, uint4 b, uint4 c, uint4 d) {
    uint4 o;
    o.x = rsum4(a.x, b.x, c.x, d.x);
    o.y = rsum4(a.y, b.y, c.y, d.y);
    o.z = rsum4(a.z, b.z, c.z, d.z);
    o.w = rsum4(a.w, b.w, c.w, d.w);
    return o;
}
__device__ __forceinline__ uint4 sum16(uint4 a, uint4 b, uint4 c, uint4 d) {
    uint4 o;
    o.x = sum4(a.x, b.x, c.x, d.x);
    o.y = sum4(a.y, b.y, c.y, d.y);
    o.z = sum4(a.z, b.z, c.z, d.z);
    o.w = sum4(a.w, b.w, c.w, d.w);
    return o;
}
__device__ __forceinline__ U8 rsum32(U8 a, U8 b, U8 c, U8 d) {
    U8 o;
    o.a = rsum16(a.a, b.a, c.a, d.a);
    o.b = rsum16(a.b, b.b, c.b, d.b);
    return o;
}
__device__ __forceinline__ U8 sum32(U8 a, U8 b, U8 c, U8 d) {
    U8 o;
    o.a = sum16(a.a, b.a, c.a, d.a);
    o.b = sum16(a.b, b.b, c.b, d.b);
    return o;
}

// ---------------- weight prep (one launch for all 3) ----------------
__global__ void prep_all(const float* __restrict__ W1s,
                         const float* __restrict__ W2s,
                         const float* __restrict__ W3s) {
    int idx = blockIdx.x * 256 + threadIdx.x;
    const int T1 = 320 * KP1, T2 = 320 * KP2;
    const float* W;
    __half* B;
    int KP, mode;
    if (idx < T1) { W = W1s; B = g_W1; KP = KP1; mode = 1; }
    else if (idx < T1 + T2) { idx -= T1; W = W2s; B = g_W2; KP = KP2; mode = 2; }
    else {
        idx -= T1 + T2;
        if (idx >= 320 * KP3) return;
        W = W3s; B = g_W3; KP = KP3; mode = 3;
    }
    int n = idx / KP, k = idx % KP;
    int src;
    if (mode == 3) src = (k < 133) ? k : (k >= 136 && k < 436) ? k - 3 : -1;
    else if (mode == 1) src = (k < K1) ? k : -1;
    else src = (k < DH) ? k : -1;
    float v = (n < 300 && src >= 0) ? W[src * 300 + n] : 0.f;
    B[(size_t)n * KP + k] = __float2half_rn(v);
}

// ---------------- gather1: m1h = sum_j relu(inph[map[j]]) ----------------
__global__ void gather_relu(const int* __restrict__ map) {
    int idx = blockIdx.x * 256 + threadIdx.x;
    if (idx >= NB * SR8) return;
    int r = idx / SR8, c = idx % SR8;
    int4 m = ((const int4*)map)[r];
    const int co = c * 16;
    U8 a = ldg32_el(g_inph + (size_t)m.x * SROW + co);
    U8 b = ldg32_el(g_inph + (size_t)m.y * SROW + co);
    U8 cc = ldg32_el(g_inph + (size_t)m.z * SROW + co);
    U8 d = ldg32_el(g_inph + (size_t)m.w * SROW + co);
    stg32_el(g_m1h + (size_t)r * SROW + co, rsum32(a, b, cc, d));   // m1h is re-read 4x
}

// ---------------- gather2: m2h = sum_j m1h[map[j]] -> [NB x 320] ----------------
__global__ void gather2(const int* __restrict__ map) {
    int idx = blockIdx.x * 256 + threadIdx.x;
    if (idx >= NB * SR8) return;
    int r = idx / SR8, c = idx % SR8;
    int4 m = ((const int4*)map)[r];
    const int co = c * 16;
    U8 a = ldg32_el(g_m1h + (size_t)m.x * SROW + co);
    U8 b = ldg32_el(g_m1h + (size_t)m.y * SROW + co);
    U8 cc = ldg32_el(g_m1h + (size_t)m.z * SROW + co);
    U8 d = ldg32_el(g_m1h + (size_t)m.w * SROW + co);
    stg32_ef(g_m2h + (size_t)r * KP2 + co, sum32(a, b, cc, d));
}

// ---------------- gather_atom: msgs = sum_j h2h[a2ib[j]] ----------------
__global__ void gather_atom(const int* __restrict__ a2ib) {
    int idx = blockIdx.x * 256 + threadIdx.x;
    if (idx >= NA * SR8) return;
    int r = idx / SR8, c = idx % SR8;
    int4 m = ((const int4*)a2ib)[r];
    const int co = c * 16;
    U8 a = ldg32_el(g_h2h + (size_t)m.x * SROW + co);
    U8 b = ldg32_el(g_h2h + (size_t)m.y * SROW + co);
    U8 cc = ldg32_el(g_h2h + (size_t)m.z * SROW + co);
    U8 d = ldg32_el(g_h2h + (size_t)m.w * SROW + co);
    stg32_ef(g_msgsh + (size_t)r * SROW + co, sum32(a, b, cc, d));
}

// ---------------- FP16 GEMM: BM=128, BN=320, templated BK, 512 thr, 3 stages ----
// Warp grid 2(m) x 8(n); warp tile 64x40. Row stride RS = 2*BK+16 bytes.
template <int MODE, int KP, int BK>
__global__ void __launch_bounds__(512)
mm_f16(const float* __restrict__ srcA,
       const float* __restrict__ bias, float* __restrict__ dOut) {
    constexpr int NCH = KP / BK;
    constexpr int RS = 2 * BK + 16;          // bytes per smem row
    constexpr int BOFF = 128 * RS;           // A block bytes
    constexpr int STG = BOFF + 320 * RS;     // stage bytes
    constexpr int KPARTS = BK / 32;          // 32-col parts per chunk (A producer)
    constexpr int NKH = BK / 16;             // k16 steps per chunk
    const __half* __restrict__ Wt = (MODE == 1) ? g_W1 : (MODE == 2) ? g_W2 : g_W3;

    extern __shared__ __align__(16) char smem[];
    const uint32_t sb = s2u(smem);
    const int tid = threadIdx.x, w = tid >> 5, lane = tid & 31;
    const int wr = w & 1, wc = w >> 1;       // warp tile 64x40
    const int rowBase = blockIdx.x * 128;

    float acc[4][5][4];
#pragma unroll
    for (int i = 0; i < 4; i++)
#pragma unroll
        for (int j = 0; j < 5; j++)
#pragma unroll
            for (int q = 0; q < 4; q++) acc[i][j][q] = 0.f;

    // ---- A producer (MODE 1/3): warp owns 8 rows, lane covers KPARTS columns ----
    __half rbuf[8 * KPARTS];
    auto loadA_regs = [&](int c) {
#pragma unroll
        for (int p = 0; p < KPARTS; p++) {
            const int k = c * BK + p * 32 + lane;
#pragma unroll
            for (int i = 0; i < 8; i++) {
                const int grow = rowBase + w * 8 + i;
                __half v = __float2half_rn(0.f);
                if (MODE == 1) {
                    if (k < K1) v = __float2half_rn(srcA[(size_t)grow * K1 + k]);
                } else if (MODE == 3) {
                    if (k < AF) v = __float2half_rn(srcA[(size_t)grow * AF + k]);
                    else if (k >= 136 && k < 436) v = g_msgsh[(size_t)grow * SROW + (k - 136)];
                }
                rbuf[p * 8 + i] = v;
            }
        }
    };
    auto stsA = [&](int st) {
#pragma unroll
        for (int p = 0; p < KPARTS; p++) {
            char* q = smem + st * STG + (w * 8) * RS + (p * 32 + lane) * 2;
#pragma unroll
            for (int i = 0; i < 8; i++) *(__half*)(q + i * RS) = rbuf[p * 8 + i];
        }
    };

    // ---- A via cp.async (MODE 2): 128 rows x (BK*2/16) segs ----
    constexpr int ASEG = BK / 8;             // 16B segs per A row
    auto cpA = [&](int c, int st) {
#pragma unroll
        for (int i = tid; i < 128 * ASEG; i += 512) {
            const int row = i / ASEG, seg = i % ASEG;
            cpa16(sb + st * STG + row * RS + seg * 16,
                  g_m2h + (size_t)(rowBase + row) * KP2 + c * BK + seg * 8);
        }
    };
    // ---- B: 320 rows x ASEG segs ----
    auto loadB = [&](int c, int st) {
#pragma unroll
        for (int i = tid; i < 320 * ASEG; i += 512) {
            const int row = i / ASEG, seg = i % ASEG;
            cpa16(sb + st * STG + BOFF + row * RS + seg * 16,
                  Wt + (size_t)row * KP + c * BK + seg * 8);
        }
    };

    // ---- prologue ----
    if (MODE != 2) {
        loadA_regs(0); stsA(0); loadB(0, 0); CP_COMMIT();
        loadA_regs(1); stsA(1); loadB(1, 1); CP_COMMIT();
        loadA_regs(2);
    } else {
        cpA(0, 0); loadB(0, 0); CP_COMMIT();
        cpA(1, 1); loadB(1, 1); CP_COMMIT();
    }

    // ldmatrix bases
    const uint32_t aOff = (uint32_t)(wr * 64 + (lane & 15)) * RS
                        + (uint32_t)(lane >> 4) * 16;
    const int bl = lane & 15;
    const uint32_t bOff = BOFF + (uint32_t)(wc * 40 + (bl & 7)) * RS
                        + (uint32_t)(bl >> 3) * 16;

    for (int c = 0; c < NCH; c++) {
        CP_WAIT1();
        __syncthreads();
        if (c + 2 < NCH) {
            const int st = (c + 2) % 3;
            if (MODE != 2) { stsA(st); }
            else          { cpA(c + 2, st); }
            loadB(c + 2, st);
        }
        CP_COMMIT();
        if (MODE != 2 && c + 3 < NCH) loadA_regs(c + 3);

        const uint32_t stp = sb + (c % 3) * STG;
#pragma unroll
        for (int kh = 0; kh < NKH; kh++) {
            uint32_t af[4][4], bf[5][2];
#pragma unroll
            for (int mt = 0; mt < 4; mt++)
                ldmx4(af[mt], stp + aOff + mt * (16 * RS) + kh * 32);
#pragma unroll
            for (int nt = 0; nt < 5; nt++)
                ldmx2(bf[nt], stp + bOff + nt * (8 * RS) + kh * 32);
#pragma unroll
            for (int mt = 0; mt < 4; mt++)
#pragma unroll
                for (int nt = 0; nt < 5; nt++)
                    mma_f16(acc[mt][nt], af[mt], bf[nt]);
        }
    }

    if (MODE == 3) {
        // fused per-molecule mean readout: 128 rows = 4 molecules
        const int molBase = blockIdx.x * 4 + wr * 2;
#pragma unroll
        for (int mtb = 0; mtb < 4; mtb += 2) {
#pragma unroll
            for (int nt = 0; nt < 5; nt++) {
                const int col2 = wc * 40 + nt * 8 + (lane & 3) * 2;
                float b0 = 0.f, b1 = 0.f;
                if (col2 < DH) { b0 = bias[col2]; b1 = bias[col2 + 1]; }
                float s0 = 0.f, s1 = 0.f;
#pragma unroll
                for (int p = 0; p < 2; p++) {
#pragma unroll
                    for (int h = 0; h < 2; h++) {
                        s0 += fmaxf(acc[mtb + p][nt][h * 2]     + b0, 0.f);
                        s1 += fmaxf(acc[mtb + p][nt][h * 2 + 1] + b1, 0.f);
                    }
                }
#pragma unroll
                for (int off = 16; off >= 4; off >>= 1) {
                    s0 += __shfl_down_sync(0xFFFFFFFFu, s0, off);
                    s1 += __shfl_down_sync(0xFFFFFFFFu, s1, off);
                }
                if (lane < 4) {
                    const int colw = wc * 40 + nt * 8 + lane * 2;
                    if (colw < DH) {
                        const int mol = molBase + (mtb >> 1);
                        float2 v;
                        v.x = s0 * 0.03125f;
                        v.y = s1 * 0.03125f;
                        *(float2*)&dOut[(size_t)mol * OUTC + colw] = v;
                    }
                }
            }
        }
    } else {
        __half* __restrict__ OUTp = (MODE == 1) ? g_inph : g_h2h;
        const int crow = lane >> 2, cc0 = (lane & 3) * 2;
#pragma unroll
        for (int mt = 0; mt < 4; mt++) {
#pragma unroll
            for (int nt = 0; nt < 5; nt++) {
                const int col = wc * 40 + nt * 8 + cc0;
                if (col >= DH) continue;
#pragma unroll
                for (int half = 0; half < 2; half++) {
                    const int grow = rowBase + wr * 64 + mt * 16 + crow + half * 8;
                    const size_t o = (size_t)grow * SROW + col;
                    float v0 = acc[mt][nt][half * 2];
                    float v1 = acc[mt][nt][half * 2 + 1];
                    if (MODE == 2) {
                        float2 pv = __half22float2(*(const __half2*)&g_inph[o]);
                        v0 = fmaxf(pv.x + v0, 0.f);
                        v1 = fmaxf(pv.y + v1, 0.f);
                    }
                    *(__half2*)&OUTp[o] = __floats2half2_rn(v0, v1);
                }
            }
        }
    }
}

// ---------------- global-feature concat ----------------
__global__ void glob_copy(const float* __restrict__ g, float* __restrict__ out) {
    int idx = blockIdx.x * 256 + threadIdx.x;
    if (idx >= NM * 32) return;
    int mol = idx >> 5, j4 = idx & 31;
    float4 v = ((const float4*)g)[mol * 32 + j4];
    *(float4*)&out[(size_t)mol * OUTC + 300 + 4 * j4] = v;
}

// ---------------- launch ----------------
extern "C" void kernel_launch(void* const* d_in, const int* in_sizes, int n_in,
                              void* d_out, int out_size) {
    const float* atom_features   = (const float*)d_in[0];
    const float* f_ini           = (const float*)d_in[1];
    const float* global_features = (const float*)d_in[2];
    const float* W_i             = (const float*)d_in[3];
    const float* W_h             = (const float*)d_in[4];
    const float* W_o             = (const float*)d_in[5];
    const float* b_o             = (const float*)d_in[6];
    const int*   a2ib            = (const int*)d_in[7];
    const int*   mapping         = (const int*)d_in[8];
    float* out = (float*)d_out;

    const int SM32 = 3 * (448 * 80);    // 107520 (BK=32)
    const int SM64 = 3 * (448 * 144);   // 193536 (BK=64)
    static bool cfg = false;
    if (!cfg) {
        cudaFuncSetAttribute(mm_f16<1, KP1, 32>, cudaFuncAttributeMaxDynamicSharedMemorySize, SM32);
        cudaFuncSetAttribute(mm_f16<2, KP2, 64>, cudaFuncAttributeMaxDynamicSharedMemorySize, SM64);
        cudaFuncSetAttribute(mm_f16<3, KP3, 64>, cudaFuncAttributeMaxDynamicSharedMemorySize, SM64);
        cfg = true;
    }

    glob_copy<<<(NM * 32 + 255) / 256, 256>>>(global_features, out);
    prep_all<<<(320 * (KP1 + KP2 + KP3) + 255) / 256, 256>>>(W_i, W_h, W_o);

    // 1) inp = f_ini @ W_i  (BK=32)
    mm_f16<1, KP1, 32><<<NB / 128, 512, SM32>>>(f_ini, nullptr, nullptr);
    // 2) m1 = sum relu(inp[mapping])   [m1h stored evict_last: re-read 4x]
    gather_relu<<<(NB * SR8 + 255) / 256, 256>>>(mapping);
    // 3) m2 = sum m1[mapping]
    gather2<<<(NB * SR8 + 255) / 256, 256>>>(mapping);
    // 4) h2 = relu(inp + m2 @ W_h)  (BK=64: half the syncs)
    mm_f16<2, KP2, 64><<<NB / 128, 512, SM64>>>(nullptr, nullptr, nullptr);
    // 5) msgs = sum h2[a2ib]
    gather_atom<<<(NA * SR8 + 255) / 256, 256>>>(a2ib);
    // 6+7) out = mean(relu([atomF | msgs] @ W_o + b_o))  (BK=64)
    mm_f16<3, KP3, 64><<<NA / 128, 512, SM64>>>(atom_features, b_o, out);
}